// round 14
// baseline (speedup 1.0000x reference)
#include <cuda_runtime.h>
#include <cuda_fp16.h>
#include <cstdint>

#define Bz 4
#define Nn 2048
#define NF 512
#define ND 64
#define NH 4
#define NC 64
#define MAX_DEG 128
#define ALPHA 0.2f
#define PADF 36

// ---------------- scratch -----------------------------------------------------
__device__ __align__(16) __half g_h [Bz * Nn * NH * ND];  // fp16 [b][n][256] 4MB
__device__ __align__(16) float  g_h1[Bz * Nn * NH * ND];  // tf32-rounded    8MB
__device__ __align__(16) __half g_g [Bz * Nn * NC];       // fp16 [b][n][64] 1MB
__device__ __align__(16) float  g_W1t[NH * ND * NF];      // tf32 [256][512]
__device__ __align__(16) float  g_W2t[NC * NH * ND];      // tf32 [64][256]
__device__ float g_ssrc[Bz * NH * Nn];
__device__ float g_sdst[Bz * NH * Nn];
__device__ float g_tsrc[Bz * Nn];
__device__ float g_tdst[Bz * Nn];
__device__ __align__(16) int g_cols[Nn * MAX_DEG];
__device__ int   g_deg[Nn];

// ---------------- helpers ------------------------------------------------------
__device__ __forceinline__ float totf(float x) {
    uint32_t u;
    asm("cvt.rna.tf32.f32 %0, %1;" : "=r"(u) : "f"(x));
    return __uint_as_float(u);
}
__device__ __forceinline__ uint32_t smem_u32(const void* p) {
    uint32_t a;
    asm("{ .reg .u64 t; cvta.to.shared.u64 t, %1; cvt.u32.u64 %0, t; }" : "=r"(a) : "l"(p));
    return a;
}
__device__ __forceinline__ void cp16(uint32_t dst, const void* src) {
    asm volatile("cp.async.ca.shared.global [%0], [%1], 16;" :: "r"(dst), "l"(src));
}
#define CP_COMMIT() asm volatile("cp.async.commit_group;" ::: "memory")
#define CP_WAIT(n)  asm volatile("cp.async.wait_group %0;" :: "n"(n) : "memory")
__device__ __forceinline__ void mma8(float* c,
                                     uint32_t a0, uint32_t a1, uint32_t a2, uint32_t a3,
                                     uint32_t b0, uint32_t b1) {
    asm volatile(
        "mma.sync.aligned.m16n8k8.row.col.f32.tf32.tf32.f32 "
        "{%0,%1,%2,%3}, {%4,%5,%6,%7}, {%8,%9}, {%0,%1,%2,%3};"
        : "+f"(c[0]), "+f"(c[1]), "+f"(c[2]), "+f"(c[3])
        : "r"(a0), "r"(a1), "r"(a2), "r"(a3), "r"(b0), "r"(b1));
}
__device__ __forceinline__ float edge_e(float si, float sdm) {
    float z = si + sdm;
    float lr = z > 0.f ? z : ALPHA * z;
    return __expf(-lr);
}

// ---------------- CSR build (float4 + nibble scan, MLP=2) -----------------------
__global__ void build_csr_kernel(const float* __restrict__ adj) {
    int row  = (blockIdx.x * blockDim.x + threadIdx.x) >> 5;
    int lane = threadIdx.x & 31;
    if (row >= Nn) return;
    const float4* ar = reinterpret_cast<const float4*>(adj + (size_t)row * Nn);
    int base = 0;
    float4 v = ar[lane];
#pragma unroll 1
    for (int it = 0; it < 16; ++it) {
        float4 cur = v;
        if (it < 15) v = ar[(it + 1) * 32 + lane];
        int c0 = it * 128 + lane * 4;
        unsigned nib = (cur.x != 0.f ? 1u : 0u) | (cur.y != 0.f ? 2u : 0u)
                     | (cur.z != 0.f ? 4u : 0u) | (cur.w != 0.f ? 8u : 0u);
        int cnt = __popc(nib);
        int sc = cnt;
#pragma unroll
        for (int o = 1; o < 32; o <<= 1) {
            int t = __shfl_up_sync(0xffffffffu, sc, o);
            if (lane >= o) sc += t;
        }
        int pos = base + sc - cnt;
        int total = __shfl_sync(0xffffffffu, sc, 31);
#pragma unroll
        for (int j = 0; j < 4; j++)
            if ((nib >> j) & 1u) {
                if (pos < MAX_DEG) g_cols[row * MAX_DEG + pos] = c0 + j;
                pos++;
            }
        base += total;
    }
    if (lane == 0) g_deg[row] = base < MAX_DEG ? base : MAX_DEG;
}

// ---------------- transposes (with tf32 convert) --------------------------------
__global__ void transposeW1_kernel(const float* __restrict__ W1) {
    __shared__ float t[32][33];
    int h = blockIdx.z, k0 = blockIdx.x * 32, d0 = blockIdx.y * 32;
    int tx = threadIdx.x, ty = threadIdx.y;
    const float* Wb = W1 + (size_t)h * NF * ND;
#pragma unroll
    for (int i = 0; i < 4; i++) t[ty + i * 8][tx] = Wb[(size_t)(k0 + ty + i * 8) * ND + d0 + tx];
    __syncthreads();
#pragma unroll
    for (int i = 0; i < 4; i++)
        g_W1t[(size_t)(h * 64 + d0 + ty + i * 8) * NF + k0 + tx] = totf(t[tx][ty + i * 8]);
}
__global__ void transposeW2_kernel(const float* __restrict__ W2) {
    __shared__ float t[32][33];
    int k0 = blockIdx.x * 32, c0 = blockIdx.y * 32;
    int tx = threadIdx.x, ty = threadIdx.y;
#pragma unroll
    for (int i = 0; i < 4; i++) t[ty + i * 8][tx] = W2[(size_t)(k0 + ty + i * 8) * NC + c0 + tx];
    __syncthreads();
#pragma unroll
    for (int i = 0; i < 4; i++)
        g_W2t[(size_t)(c0 + ty + i * 8) * (NH * ND) + k0 + tx] = totf(t[tx][ty + i * 8]);
}

// ---------------- gemm1: CTA 64x128 (4 warps, warp tile 32x64), 256 CTAs --------
// grid (128, 2). 3 CTAs/SM resident -> 12 warps/SM. Fused s_src/s_dst epilogue.
__global__ void __launch_bounds__(128, 3) gemm1_mma(const float* __restrict__ X,
                                                    const float* __restrict__ a1) {
    extern __shared__ float sm[];
    float* sA  = sm;                      // [2][64][36]
    float* sB  = sm + 2 * 64 * PADF;      // [2][128][36]
    float* sa1 = sB + 2 * 128 * PADF;     // [512]
    const int tid = threadIdx.x, lane = tid & 31, warp = tid >> 5;
    const int wm = warp & 1, wn = warp >> 1;
    const int g = lane >> 2, tig = lane & 3;
    const int row0 = blockIdx.x * 64, col0 = blockIdx.y * 128;
    sa1[tid] = a1[tid];             sa1[tid + 128] = a1[tid + 128];
    sa1[tid + 256] = a1[tid + 256]; sa1[tid + 384] = a1[tid + 384];

    // A: 64 rows x 32 k; 2 threads/row, 16 floats (4 cp16) each
    const float* gA = X     + (size_t)(row0 + (tid >> 1)) * NF + (tid & 1) * 16;
    // B: 128 rows x 32 k; 1 thread/row, 32 floats (8 cp16) each
    const float* gB = g_W1t + (size_t)(col0 + tid) * NF;
    const uint32_t dA = smem_u32(&sA[(tid >> 1) * PADF + (tid & 1) * 16]);
    const uint32_t dB = smem_u32(&sB[tid * PADF]);
    const uint32_t A_STRIDE = 64 * PADF * 4, B_STRIDE = 128 * PADF * 4;

#define ISSUE(buf, kt)                                                    \
    do {                                                                  \
        _Pragma("unroll")                                                 \
        for (int i = 0; i < 4; i++)                                       \
            cp16(dA + (buf) * A_STRIDE + 16 * i, gA + (kt) * 32 + 4 * i); \
        _Pragma("unroll")                                                 \
        for (int i = 0; i < 8; i++)                                       \
            cp16(dB + (buf) * B_STRIDE + 16 * i, gB + (kt) * 32 + 4 * i); \
        CP_COMMIT();                                                      \
    } while (0)

    float c[2][8][4];
#pragma unroll
    for (int i = 0; i < 2; i++)
#pragma unroll
        for (int j = 0; j < 8; j++)
#pragma unroll
            for (int q = 0; q < 4; q++) c[i][j][q] = 0.f;

    ISSUE(0, 0);
#pragma unroll 1
    for (int kt = 0; kt < 16; ++kt) {
        const int buf = kt & 1;
        if (kt < 15) { ISSUE(buf ^ 1, kt + 1); CP_WAIT(1); }
        else         { CP_WAIT(0); }
        __syncthreads();
        const float* A0 = sA + buf * 64 * PADF;
        const float* B0 = sB + buf * 128 * PADF;
#pragma unroll
        for (int s8 = 0; s8 < 4; ++s8) {
            const int kf = s8 * 8 + tig;
            uint32_t af[2][4];
#pragma unroll
            for (int ma = 0; ma < 2; ma++) {
                const float* ar0 = A0 + (wm * 32 + ma * 16 + g) * PADF;
                af[ma][0] = __float_as_uint(ar0[kf]);
                af[ma][1] = __float_as_uint(ar0[8 * PADF + kf]);
                af[ma][2] = __float_as_uint(ar0[kf + 4]);
                af[ma][3] = __float_as_uint(ar0[8 * PADF + kf + 4]);
            }
#pragma unroll
            for (int j = 0; j < 8; j++) {
                const float* br0 = B0 + (wn * 64 + 8 * j + g) * PADF;
                uint32_t b0 = __float_as_uint(br0[kf]);
                uint32_t b1 = __float_as_uint(br0[kf + 4]);
                mma8(c[0][j], af[0][0], af[0][1], af[0][2], af[0][3], b0, b1);
                mma8(c[1][j], af[1][0], af[1][1], af[1][2], af[1][3], b0, b1);
            }
        }
        __syncthreads();
    }
#undef ISSUE

    // epilogue: store h rows + fused s_src/s_dst (warp's 64 cols == one head)
    const int head = blockIdx.y * 2 + wn;
    const float* ahs = sa1 + head * 128;
#pragma unroll
    for (int ma = 0; ma < 2; ma++) {
        float slo = 0.f, dlo = 0.f, shi = 0.f, dhi = 0.f;
#pragma unroll
        for (int j = 0; j < 8; j++) {
            const int col = 8 * j + 2 * tig;
            float w0 = ahs[col], w1 = ahs[col + 1];
            float u0 = ahs[64 + col], u1 = ahs[64 + col + 1];
            slo += c[ma][j][0] * w0 + c[ma][j][1] * w1;
            dlo += c[ma][j][0] * u0 + c[ma][j][1] * u1;
            shi += c[ma][j][2] * w0 + c[ma][j][3] * w1;
            dhi += c[ma][j][2] * u0 + c[ma][j][3] * u1;
        }
#pragma unroll
        for (int o = 1; o < 4; o <<= 1) {
            slo += __shfl_xor_sync(0xffffffffu, slo, o);
            dlo += __shfl_xor_sync(0xffffffffu, dlo, o);
            shi += __shfl_xor_sync(0xffffffffu, shi, o);
            dhi += __shfl_xor_sync(0xffffffffu, dhi, o);
        }
        const int rlo = row0 + wm * 32 + ma * 16 + g;
        const int rhi = rlo + 8;
        __half2* dst0 = (__half2*)g_h + ((size_t)rlo * 256 + head * 64) / 2;
        __half2* dst1 = (__half2*)g_h + ((size_t)rhi * 256 + head * 64) / 2;
#pragma unroll
        for (int j = 0; j < 8; j++) {
            const int hc = 4 * j + tig;
            dst0[hc] = __floats2half2_rn(c[ma][j][0], c[ma][j][1]);
            dst1[hc] = __floats2half2_rn(c[ma][j][2], c[ma][j][3]);
        }
        if (tig == 0) {
            int b0i = rlo >> 11, n0i = rlo & (Nn - 1);
            int b1i = rhi >> 11, n1i = rhi & (Nn - 1);
            g_ssrc[(b0i * NH + head) * Nn + n0i] = slo;
            g_sdst[(b0i * NH + head) * Nn + n0i] = dlo;
            g_ssrc[(b1i * NH + head) * Nn + n1i] = shi;
            g_sdst[(b1i * NH + head) * Nn + n1i] = dhi;
        }
    }
}

// ---------------- attn1: warp per (b,n), fp16 gather (round-9 form) -------------
__global__ void attn1_kernel() {
    int gw   = (blockIdx.x * blockDim.x + threadIdx.x) >> 5;   // b*Nn + n
    int lane = threadIdx.x & 31;
    if (gw >= Bz * Nn) return;
    int n = gw & (Nn - 1), b = gw >> 11;
    int head = lane >> 3;
    const uint4* hb = reinterpret_cast<const uint4*>(
        g_h + (size_t)b * Nn * 256 + lane * 8);
    const float* sdp = g_sdst + (size_t)(b * NH + head) * Nn;
    float si = g_ssrc[(size_t)(b * NH + head) * Nn + n];
    int dg = g_deg[n];
    const int* cr = g_cols + n * MAX_DEG;
    float acc[8] = {};
    float den = 0.f;
    int k = 0;
    int4 nx = *(const int4*)cr;
    for (; k + 4 <= dg; k += 4) {
        int4 mm = nx;
        if (k + 8 <= dg) nx = *(const int4*)(cr + k + 4);
        float d0 = sdp[mm.x], d1 = sdp[mm.y], d2 = sdp[mm.z], d3 = sdp[mm.w];
        uint4 r0 = hb[(size_t)mm.x * 32];
        uint4 r1 = hb[(size_t)mm.y * 32];
        uint4 r2 = hb[(size_t)mm.z * 32];
        uint4 r3 = hb[(size_t)mm.w * 32];
        float e0 = edge_e(si, d0), e1 = edge_e(si, d1);
        float e2 = edge_e(si, d2), e3 = edge_e(si, d3);
        den += (e0 + e1) + (e2 + e3);
        const uint32_t* w0 = &r0.x; const uint32_t* w1 = &r1.x;
        const uint32_t* w2 = &r2.x; const uint32_t* w3 = &r3.x;
#pragma unroll
        for (int p = 0; p < 4; p++) {
            float2 f0 = __half22float2(*(const __half2*)&w0[p]);
            float2 f1 = __half22float2(*(const __half2*)&w1[p]);
            float2 f2 = __half22float2(*(const __half2*)&w2[p]);
            float2 f3 = __half22float2(*(const __half2*)&w3[p]);
            acc[2 * p]     += e0 * f0.x + e1 * f1.x + e2 * f2.x + e3 * f3.x;
            acc[2 * p + 1] += e0 * f0.y + e1 * f1.y + e2 * f2.y + e3 * f3.y;
        }
    }
    for (; k < dg; k++) {
        int m = cr[k];
        float e = edge_e(si, sdp[m]);
        uint4 r = hb[(size_t)m * 32];
        const uint32_t* w = &r.x;
        den += e;
#pragma unroll
        for (int p = 0; p < 4; p++) {
            float2 f = __half22float2(*(const __half2*)&w[p]);
            acc[2 * p]     += e * f.x;
            acc[2 * p + 1] += e * f.y;
        }
    }
    float inv = 1.0f / den;
    float o[8];
#pragma unroll
    for (int j = 0; j < 8; j++) {
        o[j] = acc[j] * inv;
        o[j] = o[j] > 0.f ? o[j] : expm1f(o[j]);
        o[j] = totf(o[j]);   // pre-round for gemm2's tf32 MMA
    }
    float* dst = g_h1 + (size_t)gw * 256 + lane * 8;
    *(float4*)dst       = make_float4(o[0], o[1], o[2], o[3]);
    *(float4*)(dst + 4) = make_float4(o[4], o[5], o[6], o[7]);
}

// ---------------- gemm2: g = h1 @ W2t^T, cp.async pipeline, fused t dots --------
__global__ void __launch_bounds__(64, 6) gemm2_mma(const float* __restrict__ a2) {
    extern __shared__ float sm[];
    float* sA  = sm;                     // [2][64][36]
    float* sB  = sm + 2 * 64 * PADF;     // [2][64][36]
    float* sa2 = sB + 2 * 64 * PADF;     // [128]
    const int tid = threadIdx.x, lane = tid & 31, warp = tid >> 5;
    const int g = lane >> 2, tig = lane & 3;
    const int row0 = blockIdx.x * 64;
    const int K = NH * ND;  // 256
    sa2[tid] = a2[tid]; sa2[tid + 64] = a2[tid + 64];

    const float* gA = g_h1  + (size_t)(row0 + tid) * K;
    const float* gB = g_W2t + (size_t)tid * K;
    const uint32_t dA = smem_u32(&sA[tid * PADF]);
    const uint32_t dB = smem_u32(&sB[tid * PADF]);
    const uint32_t STRIDE = 64 * PADF * 4;

#define ISSUE2(buf, kt)                                                \
    do {                                                               \
        _Pragma("unroll")                                              \
        for (int i = 0; i < 8; i++)                                    \
            cp16(dA + (buf) * STRIDE + 16 * i, gA + (kt) * 32 + 4 * i);\
        _Pragma("unroll")                                              \
        for (int i = 0; i < 8; i++)                                    \
            cp16(dB + (buf) * STRIDE + 16 * i, gB + (kt) * 32 + 4 * i);\
        CP_COMMIT();                                                   \
    } while (0)

    float c[2][8][4];
#pragma unroll
    for (int i = 0; i < 2; i++)
#pragma unroll
        for (int j = 0; j < 8; j++)
#pragma unroll
            for (int q = 0; q < 4; q++) c[i][j][q] = 0.f;

    ISSUE2(0, 0);
#pragma unroll 1
    for (int kt = 0; kt < 8; ++kt) {
        const int buf = kt & 1;
        if (kt < 7) { ISSUE2(buf ^ 1, kt + 1); CP_WAIT(1); }
        else        { CP_WAIT(0); }
        __syncthreads();
        const float* A0 = sA + buf * 64 * PADF;
        const float* B0 = sB + buf * 64 * PADF;
#pragma unroll
        for (int s8 = 0; s8 < 4; ++s8) {
            const int kf = s8 * 8 + tig;
            uint32_t af[2][4];
#pragma unroll
            for (int ma = 0; ma < 2; ma++) {
                const float* ar0 = A0 + (warp * 32 + ma * 16 + g) * PADF;
                af[ma][0] = __float_as_uint(ar0[kf]);
                af[ma][1] = __float_as_uint(ar0[8 * PADF + kf]);
                af[ma][2] = __float_as_uint(ar0[kf + 4]);
                af[ma][3] = __float_as_uint(ar0[8 * PADF + kf + 4]);
            }
#pragma unroll
            for (int j = 0; j < 8; j++) {
                const float* br0 = B0 + (8 * j + g) * PADF;
                uint32_t b0 = __float_as_uint(br0[kf]);
                uint32_t b1 = __float_as_uint(br0[kf + 4]);
                mma8(c[0][j], af[0][0], af[0][1], af[0][2], af[0][3], b0, b1);
                mma8(c[1][j], af[1][0], af[1][1], af[1][2], af[1][3], b0, b1);
            }
        }
        __syncthreads();
    }
#undef ISSUE2

#pragma unroll
    for (int ma = 0; ma < 2; ma++) {
        float slo = 0.f, dlo = 0.f, shi = 0.f, dhi = 0.f;
#pragma unroll
        for (int j = 0; j < 8; j++) {
            const int col = 8 * j + 2 * tig;
            float w0 = sa2[col], w1 = sa2[col + 1];
            float u0 = sa2[64 + col], u1 = sa2[64 + col + 1];
            slo += c[ma][j][0] * w0 + c[ma][j][1] * w1;
            dlo += c[ma][j][0] * u0 + c[ma][j][1] * u1;
            shi += c[ma][j][2] * w0 + c[ma][j][3] * w1;
            dhi += c[ma][j][2] * u0 + c[ma][j][3] * u1;
        }
#pragma unroll
        for (int o = 1; o < 4; o <<= 1) {
            slo += __shfl_xor_sync(0xffffffffu, slo, o);
            dlo += __shfl_xor_sync(0xffffffffu, dlo, o);
            shi += __shfl_xor_sync(0xffffffffu, shi, o);
            dhi += __shfl_xor_sync(0xffffffffu, dhi, o);
        }
        const int rlo = row0 + warp * 32 + ma * 16 + g;
        const int rhi = rlo + 8;
        __half2* dst0 = (__half2*)g_g + (size_t)rlo * 32;
        __half2* dst1 = (__half2*)g_g + (size_t)rhi * 32;
#pragma unroll
        for (int j = 0; j < 8; j++) {
            const int hc = 4 * j + tig;
            dst0[hc] = __floats2half2_rn(c[ma][j][0], c[ma][j][1]);
            dst1[hc] = __floats2half2_rn(c[ma][j][2], c[ma][j][3]);
        }
        if (tig == 0) {
            g_tsrc[rlo] = slo; g_tdst[rlo] = dlo;
            g_tsrc[rhi] = shi; g_tdst[rhi] = dhi;
        }
    }
}

// ---------------- attn2: warp per (b,n), shfl-deduped edge scalars + elu --------
__global__ void attn2_kernel(float* __restrict__ out) {
    int gw   = (blockIdx.x * blockDim.x + threadIdx.x) >> 5;
    int lane = threadIdx.x & 31;
    if (gw >= Bz * Nn) return;
    int n = gw & (Nn - 1);
    int b = gw >> 11;
    int sub = lane & 3;
    const __half2* gb = (const __half2*)g_g + (size_t)b * Nn * 32 + lane;
    const float*   td = g_tdst + (size_t)b * Nn;
    float ti = g_tsrc[gw];
    int dg = g_deg[n];
    const int* cr = g_cols + n * MAX_DEG;
    float2 acc = {0.f, 0.f};
    float den = 0.f;
    int k = 0;
    int4 nx = *(const int4*)cr;
    for (; k + 4 <= dg; k += 4) {
        int4 mm = nx;
        if (k + 8 <= dg) nx = *(const int4*)(cr + k + 4);
        int midx = (sub == 0) ? mm.x : (sub == 1) ? mm.y : (sub == 2) ? mm.z : mm.w;
        float ev = edge_e(ti, td[midx]);
        float e0 = __shfl_sync(0xffffffffu, ev, 0);
        float e1 = __shfl_sync(0xffffffffu, ev, 1);
        float e2 = __shfl_sync(0xffffffffu, ev, 2);
        float e3 = __shfl_sync(0xffffffffu, ev, 3);
        __half2 v0 = gb[(size_t)mm.x * 32];
        __half2 v1 = gb[(size_t)mm.y * 32];
        __half2 v2 = gb[(size_t)mm.z * 32];
        __half2 v3 = gb[(size_t)mm.w * 32];
        den += (e0 + e1) + (e2 + e3);
        float2 f0 = __half22float2(v0), f1 = __half22float2(v1);
        float2 f2 = __half22float2(v2), f3 = __half22float2(v3);
        acc.x += e0 * f0.x + e1 * f1.x + e2 * f2.x + e3 * f3.x;
        acc.y += e0 * f0.y + e1 * f1.y + e2 * f2.y + e3 * f3.y;
    }
    for (; k < dg; k++) {
        int m = cr[k];
        float e = edge_e(ti, td[m]);
        float2 f = __half22float2(gb[(size_t)m * 32]);
        den += e;
        acc.x += e * f.x; acc.y += e * f.y;
    }
    float inv = 1.0f / den;
    float o0 = acc.x * inv, o1 = acc.y * inv;
    o0 = o0 > 0.f ? o0 : expm1f(o0);
    o1 = o1 > 0.f ? o1 : expm1f(o1);
    float* dst = out + (size_t)gw * NC + lane * 2;
    dst[0] = o0; dst[1] = o1;
}

// ---------------- launch -----------------------------------------------------------
extern "C" void kernel_launch(void* const* d_in, const int* in_sizes, int n_in,
                              void* d_out, int out_size) {
    const float* x   = (const float*)d_in[0];
    const float* adj = (const float*)d_in[1];
    const float* W1  = (const float*)d_in[2];
    const float* a1  = (const float*)d_in[3];
    const float* W2  = (const float*)d_in[4];
    const float* a2  = (const float*)d_in[5];
    float* out = (float*)d_out;

    const int smem1 = (2 * 64 * PADF + 2 * 128 * PADF + 512) * 4;  // 57344 B
    const int smem2 = (2 * 64 * PADF + 2 * 64 * PADF + 128) * 4;   // 37376 B
    cudaFuncSetAttribute(gemm1_mma, cudaFuncAttributeMaxDynamicSharedMemorySize, smem1);
    cudaFuncSetAttribute(gemm2_mma, cudaFuncAttributeMaxDynamicSharedMemorySize, smem2);

    build_csr_kernel<<<(Nn * 32) / 256, 256>>>(adj);
    transposeW1_kernel<<<dim3(16, 2, 4), dim3(32, 8)>>>(W1);
    transposeW2_kernel<<<dim3(8, 2), dim3(32, 8)>>>(W2);
    gemm1_mma<<<dim3(128, 2), 128, smem1>>>(x, a1);     // profiled (4th)
    attn1_kernel<<<(Bz * Nn * 32) / 256, 256>>>();
    gemm2_mma<<<128, 64, smem2>>>(a2);
    attn2_kernel<<<(Bz * Nn * 32) / 256, 256>>>(out);
}

// round 15
// speedup vs baseline: 1.3345x; 1.3345x over previous
#include <cuda_runtime.h>
#include <cuda_fp16.h>
#include <cstdint>

#define Bz 4
#define Nn 2048
#define NF 512
#define ND 64
#define NH 4
#define NC 64
#define MAX_DEG 128
#define ALPHA 0.2f
#define PADH 40   // half-stride per smem row (conflict-free fragments)

// ---------------- scratch -----------------------------------------------------
__device__ __align__(16) __half g_Xh[Bz * Nn * NF];       // fp16 X          8MB
__device__ __align__(16) __half g_h [Bz * Nn * NH * ND];  // fp16 [b][n][256] 4MB
__device__ __align__(16) __half g_h1[Bz * Nn * NH * ND];  // fp16            4MB
__device__ __align__(16) __half g_g [Bz * Nn * NC];       // fp16 [b][n][64] 1MB
__device__ __align__(16) __half g_W1t[NH * ND * NF];      // fp16 [256][512]
__device__ __align__(16) __half g_W2t[NC * NH * ND];      // fp16 [64][256]
__device__ float g_ssrc[Bz * NH * Nn];
__device__ float g_sdst[Bz * NH * Nn];
__device__ float g_tsrc[Bz * Nn];
__device__ float g_tdst[Bz * Nn];
__device__ __align__(16) int g_cols[Nn * MAX_DEG];
__device__ int   g_deg[Nn];

// ---------------- helpers ------------------------------------------------------
__device__ __forceinline__ uint32_t smem_u32(const void* p) {
    uint32_t a;
    asm("{ .reg .u64 t; cvta.to.shared.u64 t, %1; cvt.u32.u64 %0, t; }" : "=r"(a) : "l"(p));
    return a;
}
__device__ __forceinline__ void cp16(uint32_t dst, const void* src) {
    asm volatile("cp.async.ca.shared.global [%0], [%1], 16;" :: "r"(dst), "l"(src));
}
#define CP_COMMIT() asm volatile("cp.async.commit_group;" ::: "memory")
#define CP_WAIT(n)  asm volatile("cp.async.wait_group %0;" :: "n"(n) : "memory")
__device__ __forceinline__ void mma16(float* c,
                                      uint32_t a0, uint32_t a1, uint32_t a2, uint32_t a3,
                                      uint32_t b0, uint32_t b1) {
    asm volatile(
        "mma.sync.aligned.m16n8k16.row.col.f32.f16.f16.f32 "
        "{%0,%1,%2,%3}, {%4,%5,%6,%7}, {%8,%9}, {%0,%1,%2,%3};"
        : "+f"(c[0]), "+f"(c[1]), "+f"(c[2]), "+f"(c[3])
        : "r"(a0), "r"(a1), "r"(a2), "r"(a3), "r"(b0), "r"(b1));
}
__device__ __forceinline__ float edge_e(float si, float sdm) {
    float z = si + sdm;
    float lr = z > 0.f ? z : ALPHA * z;
    return __expf(-lr);
}
__device__ __forceinline__ uint32_t h2u(__half2 h) {
    return *reinterpret_cast<uint32_t*>(&h);
}

// ---------------- convert X to fp16 ---------------------------------------------
__global__ void convertX_kernel(const float* __restrict__ X) {
    int i = blockIdx.x * blockDim.x + threadIdx.x;   // 1M float4
    float4 v = ((const float4*)X)[i];
    __half2* dst = (__half2*)g_Xh + 2 * i;
    dst[0] = __floats2half2_rn(v.x, v.y);
    dst[1] = __floats2half2_rn(v.z, v.w);
}

// ---------------- CSR build (float4 + nibble scan, MLP=2) -----------------------
__global__ void build_csr_kernel(const float* __restrict__ adj) {
    int row  = (blockIdx.x * blockDim.x + threadIdx.x) >> 5;
    int lane = threadIdx.x & 31;
    if (row >= Nn) return;
    const float4* ar = reinterpret_cast<const float4*>(adj + (size_t)row * Nn);
    int base = 0;
    float4 v = ar[lane];
#pragma unroll 1
    for (int it = 0; it < 16; ++it) {
        float4 cur = v;
        if (it < 15) v = ar[(it + 1) * 32 + lane];
        int c0 = it * 128 + lane * 4;
        unsigned nib = (cur.x != 0.f ? 1u : 0u) | (cur.y != 0.f ? 2u : 0u)
                     | (cur.z != 0.f ? 4u : 0u) | (cur.w != 0.f ? 8u : 0u);
        int cnt = __popc(nib);
        int sc = cnt;
#pragma unroll
        for (int o = 1; o < 32; o <<= 1) {
            int t = __shfl_up_sync(0xffffffffu, sc, o);
            if (lane >= o) sc += t;
        }
        int pos = base + sc - cnt;
        int total = __shfl_sync(0xffffffffu, sc, 31);
#pragma unroll
        for (int j = 0; j < 4; j++)
            if ((nib >> j) & 1u) {
                if (pos < MAX_DEG) g_cols[row * MAX_DEG + pos] = c0 + j;
                pos++;
            }
        base += total;
    }
    if (lane == 0) g_deg[row] = base < MAX_DEG ? base : MAX_DEG;
}

// ---------------- transposes (fp16 output) ---------------------------------------
__global__ void transposeW1_kernel(const float* __restrict__ W1) {
    __shared__ float t[32][33];
    int h = blockIdx.z, k0 = blockIdx.x * 32, d0 = blockIdx.y * 32;
    int tx = threadIdx.x, ty = threadIdx.y;
    const float* Wb = W1 + (size_t)h * NF * ND;
#pragma unroll
    for (int i = 0; i < 4; i++) t[ty + i * 8][tx] = Wb[(size_t)(k0 + ty + i * 8) * ND + d0 + tx];
    __syncthreads();
#pragma unroll
    for (int i = 0; i < 4; i++)
        g_W1t[(size_t)(h * 64 + d0 + ty + i * 8) * NF + k0 + tx] =
            __float2half_rn(t[tx][ty + i * 8]);
}
__global__ void transposeW2_kernel(const float* __restrict__ W2) {
    __shared__ float t[32][33];
    int k0 = blockIdx.x * 32, c0 = blockIdx.y * 32;
    int tx = threadIdx.x, ty = threadIdx.y;
#pragma unroll
    for (int i = 0; i < 4; i++) t[ty + i * 8][tx] = W2[(size_t)(k0 + ty + i * 8) * NC + c0 + tx];
    __syncthreads();
#pragma unroll
    for (int i = 0; i < 4; i++)
        g_W2t[(size_t)(c0 + ty + i * 8) * (NH * ND) + k0 + tx] =
            __float2half_rn(t[tx][ty + i * 8]);
}

// ---------------- gemm1: h = Xh @ W1t^T, fp16 m16n8k16, fused s dots -------------
// CTA 128x128, K-step 32 halfs, grid (64, 2). 8 warps = 4M x 2N, warp tile 32x64.
__global__ void __launch_bounds__(256, 2) gemm1_mma(const float* __restrict__ a1) {
    extern __shared__ __half smh[];
    __half* sA  = smh;                     // [2][128][PADH]
    __half* sB  = smh + 2 * 128 * PADH;    // [2][128][PADH]
    float*  sa1 = (float*)(smh + 4 * 128 * PADH);  // [512]
    const int tid = threadIdx.x, lane = tid & 31, warp = tid >> 5;
    const int wm = warp & 3, wn = warp >> 2;
    const int g = lane >> 2, tig = lane & 3;
    const int row0 = blockIdx.x * 128, col0 = blockIdx.y * 128;
    sa1[tid] = a1[tid]; sa1[tid + 256] = a1[tid + 256];

    // loaders: 2 threads/row, 16 halfs (2 cp16) each; kt covers 32 halfs
    const __half* gA = g_Xh  + (size_t)(row0 + (tid >> 1)) * NF + (tid & 1) * 16;
    const __half* gB = g_W1t + (size_t)(col0 + (tid >> 1)) * NF + (tid & 1) * 16;
    const uint32_t dA = smem_u32(&sA[(tid >> 1) * PADH + (tid & 1) * 16]);
    const uint32_t dB = smem_u32(&sB[(tid >> 1) * PADH + (tid & 1) * 16]);
    const uint32_t STRIDE = 128 * PADH * 2;   // bytes per buffer

#define ISSUE(buf, kt)                                                 \
    do {                                                               \
        cp16(dA + (buf) * STRIDE,      gA + (kt) * 32);                \
        cp16(dA + (buf) * STRIDE + 16, gA + (kt) * 32 + 8);            \
        cp16(dB + (buf) * STRIDE,      gB + (kt) * 32);                \
        cp16(dB + (buf) * STRIDE + 16, gB + (kt) * 32 + 8);            \
        CP_COMMIT();                                                   \
    } while (0)

    float c[2][8][4];
#pragma unroll
    for (int i = 0; i < 2; i++)
#pragma unroll
        for (int j = 0; j < 8; j++)
#pragma unroll
            for (int q = 0; q < 4; q++) c[i][j][q] = 0.f;

    ISSUE(0, 0);
#pragma unroll 1
    for (int kt = 0; kt < 16; ++kt) {
        const int buf = kt & 1;
        if (kt < 15) { ISSUE(buf ^ 1, kt + 1); CP_WAIT(1); }
        else         { CP_WAIT(0); }
        __syncthreads();
        const __half* A0 = sA + buf * 128 * PADH;
        const __half* B0 = sB + buf * 128 * PADH;
#pragma unroll
        for (int ks = 0; ks < 2; ++ks) {                // 2 x k16 per kt
            const int kb = ks * 16 + 2 * tig;
            uint32_t af[2][4];
#pragma unroll
            for (int ma = 0; ma < 2; ma++) {
                const __half* ar0 = A0 + (wm * 32 + ma * 16 + g) * PADH + kb;
                af[ma][0] = *(const uint32_t*)(ar0);
                af[ma][1] = *(const uint32_t*)(ar0 + 8 * PADH);
                af[ma][2] = *(const uint32_t*)(ar0 + 8);
                af[ma][3] = *(const uint32_t*)(ar0 + 8 * PADH + 8);
            }
#pragma unroll
            for (int j = 0; j < 8; j++) {
                const __half* br0 = B0 + (wn * 64 + 8 * j + g) * PADH + kb;
                uint32_t b0 = *(const uint32_t*)(br0);
                uint32_t b1 = *(const uint32_t*)(br0 + 8);
                mma16(c[0][j], af[0][0], af[0][1], af[0][2], af[0][3], b0, b1);
                mma16(c[1][j], af[1][0], af[1][1], af[1][2], af[1][3], b0, b1);
            }
        }
        __syncthreads();
    }
#undef ISSUE

    // epilogue: store h rows (fp16) + fused s_src/s_dst (warp's 64 cols == one head)
    const int head = blockIdx.y * 2 + wn;
    const float* ahs = sa1 + head * 128;
#pragma unroll
    for (int ma = 0; ma < 2; ma++) {
        float slo = 0.f, dlo = 0.f, shi = 0.f, dhi = 0.f;
#pragma unroll
        for (int j = 0; j < 8; j++) {
            const int col = 8 * j + 2 * tig;
            float w0 = ahs[col], w1 = ahs[col + 1];
            float u0 = ahs[64 + col], u1 = ahs[64 + col + 1];
            slo += c[ma][j][0] * w0 + c[ma][j][1] * w1;
            dlo += c[ma][j][0] * u0 + c[ma][j][1] * u1;
            shi += c[ma][j][2] * w0 + c[ma][j][3] * w1;
            dhi += c[ma][j][2] * u0 + c[ma][j][3] * u1;
        }
#pragma unroll
        for (int o = 1; o < 4; o <<= 1) {
            slo += __shfl_xor_sync(0xffffffffu, slo, o);
            dlo += __shfl_xor_sync(0xffffffffu, dlo, o);
            shi += __shfl_xor_sync(0xffffffffu, shi, o);
            dhi += __shfl_xor_sync(0xffffffffu, dhi, o);
        }
        const int rlo = row0 + wm * 32 + ma * 16 + g;
        const int rhi = rlo + 8;
        __half2* dst0 = (__half2*)g_h + ((size_t)rlo * 256 + head * 64) / 2;
        __half2* dst1 = (__half2*)g_h + ((size_t)rhi * 256 + head * 64) / 2;
#pragma unroll
        for (int j = 0; j < 8; j++) {
            const int hc = 4 * j + tig;
            dst0[hc] = __floats2half2_rn(c[ma][j][0], c[ma][j][1]);
            dst1[hc] = __floats2half2_rn(c[ma][j][2], c[ma][j][3]);
        }
        if (tig == 0) {
            int b0i = rlo >> 11, n0i = rlo & (Nn - 1);
            int b1i = rhi >> 11, n1i = rhi & (Nn - 1);
            g_ssrc[(b0i * NH + head) * Nn + n0i] = slo;
            g_sdst[(b0i * NH + head) * Nn + n0i] = dlo;
            g_ssrc[(b1i * NH + head) * Nn + n1i] = shi;
            g_sdst[(b1i * NH + head) * Nn + n1i] = dhi;
        }
    }
}

// ---------------- attn1: warp per (b,n), fp16 gather; h1 stored fp16 -------------
__global__ void attn1_kernel() {
    int gw   = (blockIdx.x * blockDim.x + threadIdx.x) >> 5;   // b*Nn + n
    int lane = threadIdx.x & 31;
    if (gw >= Bz * Nn) return;
    int n = gw & (Nn - 1), b = gw >> 11;
    int head = lane >> 3;
    const uint4* hb = reinterpret_cast<const uint4*>(
        g_h + (size_t)b * Nn * 256 + lane * 8);
    const float* sdp = g_sdst + (size_t)(b * NH + head) * Nn;
    float si = g_ssrc[(size_t)(b * NH + head) * Nn + n];
    int dg = g_deg[n];
    const int* cr = g_cols + n * MAX_DEG;
    float acc[8] = {};
    float den = 0.f;
    int k = 0;
    int4 nx = *(const int4*)cr;
    for (; k + 4 <= dg; k += 4) {
        int4 mm = nx;
        if (k + 8 <= dg) nx = *(const int4*)(cr + k + 4);
        float d0 = sdp[mm.x], d1 = sdp[mm.y], d2 = sdp[mm.z], d3 = sdp[mm.w];
        uint4 r0 = hb[(size_t)mm.x * 32];
        uint4 r1 = hb[(size_t)mm.y * 32];
        uint4 r2 = hb[(size_t)mm.z * 32];
        uint4 r3 = hb[(size_t)mm.w * 32];
        float e0 = edge_e(si, d0), e1 = edge_e(si, d1);
        float e2 = edge_e(si, d2), e3 = edge_e(si, d3);
        den += (e0 + e1) + (e2 + e3);
        const uint32_t* w0 = &r0.x; const uint32_t* w1 = &r1.x;
        const uint32_t* w2 = &r2.x; const uint32_t* w3 = &r3.x;
#pragma unroll
        for (int p = 0; p < 4; p++) {
            float2 f0 = __half22float2(*(const __half2*)&w0[p]);
            float2 f1 = __half22float2(*(const __half2*)&w1[p]);
            float2 f2 = __half22float2(*(const __half2*)&w2[p]);
            float2 f3 = __half22float2(*(const __half2*)&w3[p]);
            acc[2 * p]     += e0 * f0.x + e1 * f1.x + e2 * f2.x + e3 * f3.x;
            acc[2 * p + 1] += e0 * f0.y + e1 * f1.y + e2 * f2.y + e3 * f3.y;
        }
    }
    for (; k < dg; k++) {
        int m = cr[k];
        float e = edge_e(si, sdp[m]);
        uint4 r = hb[(size_t)m * 32];
        const uint32_t* w = &r.x;
        den += e;
#pragma unroll
        for (int p = 0; p < 4; p++) {
            float2 f = __half22float2(*(const __half2*)&w[p]);
            acc[2 * p]     += e * f.x;
            acc[2 * p + 1] += e * f.y;
        }
    }
    float inv = 1.0f / den;
    float o[8];
#pragma unroll
    for (int j = 0; j < 8; j++) {
        o[j] = acc[j] * inv;
        o[j] = o[j] > 0.f ? o[j] : expm1f(o[j]);
    }
    // store fp16 (gemm2's A operand)
    uint4 u;
    u.x = h2u(__floats2half2_rn(o[0], o[1]));
    u.y = h2u(__floats2half2_rn(o[2], o[3]));
    u.z = h2u(__floats2half2_rn(o[4], o[5]));
    u.w = h2u(__floats2half2_rn(o[6], o[7]));
    *(uint4*)(g_h1 + (size_t)gw * 256 + lane * 8) = u;
}

// ---------------- gemm2: g = h1 @ W2t^T, fp16 m16n8k16, fused t dots -------------
// CTA 64x64, 64 thr (2 warps, warp tile 32x64). grid 128. K=256 halfs (8 kt).
__global__ void __launch_bounds__(64, 6) gemm2_mma(const float* __restrict__ a2) {
    extern __shared__ __half smh[];
    __half* sA  = smh;                    // [2][64][PADH]
    __half* sB  = smh + 2 * 64 * PADH;    // [2][64][PADH]
    float*  sa2 = (float*)(smh + 4 * 64 * PADH);  // [128]
    const int tid = threadIdx.x, lane = tid & 31, warp = tid >> 5;
    const int g = lane >> 2, tig = lane & 3;
    const int row0 = blockIdx.x * 64;
    const int K = NH * ND;  // 256
    sa2[tid] = a2[tid]; sa2[tid + 64] = a2[tid + 64];

    // loaders: 1 thread/row, 32 halfs (4 cp16) per kt
    const __half* gA = g_h1  + (size_t)(row0 + tid) * K;
    const __half* gB = g_W2t + (size_t)tid * K;
    const uint32_t dA = smem_u32(&sA[tid * PADH]);
    const uint32_t dB = smem_u32(&sB[tid * PADH]);
    const uint32_t STRIDE = 64 * PADH * 2;

#define ISSUE2(buf, kt)                                                \
    do {                                                               \
        _Pragma("unroll")                                              \
        for (int i = 0; i < 4; i++)                                    \
            cp16(dA + (buf) * STRIDE + 16 * i, gA + (kt) * 32 + 8 * i);\
        _Pragma("unroll")                                              \
        for (int i = 0; i < 4; i++)                                    \
            cp16(dB + (buf) * STRIDE + 16 * i, gB + (kt) * 32 + 8 * i);\
        CP_COMMIT();                                                   \
    } while (0)

    float c[2][8][4];
#pragma unroll
    for (int i = 0; i < 2; i++)
#pragma unroll
        for (int j = 0; j < 8; j++)
#pragma unroll
            for (int q = 0; q < 4; q++) c[i][j][q] = 0.f;

    ISSUE2(0, 0);
#pragma unroll 1
    for (int kt = 0; kt < 8; ++kt) {
        const int buf = kt & 1;
        if (kt < 7) { ISSUE2(buf ^ 1, kt + 1); CP_WAIT(1); }
        else        { CP_WAIT(0); }
        __syncthreads();
        const __half* A0 = sA + buf * 64 * PADH;
        const __half* B0 = sB + buf * 64 * PADH;
#pragma unroll
        for (int ks = 0; ks < 2; ++ks) {
            const int kb = ks * 16 + 2 * tig;
            uint32_t af[2][4];
#pragma unroll
            for (int ma = 0; ma < 2; ma++) {
                const __half* ar0 = A0 + (warp * 32 + ma * 16 + g) * PADH + kb;
                af[ma][0] = *(const uint32_t*)(ar0);
                af[ma][1] = *(const uint32_t*)(ar0 + 8 * PADH);
                af[ma][2] = *(const uint32_t*)(ar0 + 8);
                af[ma][3] = *(const uint32_t*)(ar0 + 8 * PADH + 8);
            }
#pragma unroll
            for (int j = 0; j < 8; j++) {
                const __half* br0 = B0 + (8 * j + g) * PADH + kb;
                uint32_t b0 = *(const uint32_t*)(br0);
                uint32_t b1 = *(const uint32_t*)(br0 + 8);
                mma16(c[0][j], af[0][0], af[0][1], af[0][2], af[0][3], b0, b1);
                mma16(c[1][j], af[1][0], af[1][1], af[1][2], af[1][3], b0, b1);
            }
        }
        __syncthreads();
    }
#undef ISSUE2

#pragma unroll
    for (int ma = 0; ma < 2; ma++) {
        float slo = 0.f, dlo = 0.f, shi = 0.f, dhi = 0.f;
#pragma unroll
        for (int j = 0; j < 8; j++) {
            const int col = 8 * j + 2 * tig;
            float w0 = sa2[col], w1 = sa2[col + 1];
            float u0 = sa2[64 + col], u1 = sa2[64 + col + 1];
            slo += c[ma][j][0] * w0 + c[ma][j][1] * w1;
            dlo += c[ma][j][0] * u0 + c[ma][j][1] * u1;
            shi += c[ma][j][2] * w0 + c[ma][j][3] * w1;
            dhi += c[ma][j][2] * u0 + c[ma][j][3] * u1;
        }
#pragma unroll
        for (int o = 1; o < 4; o <<= 1) {
            slo += __shfl_xor_sync(0xffffffffu, slo, o);
            dlo += __shfl_xor_sync(0xffffffffu, dlo, o);
            shi += __shfl_xor_sync(0xffffffffu, shi, o);
            dhi += __shfl_xor_sync(0xffffffffu, dhi, o);
        }
        const int rlo = row0 + warp * 32 + ma * 16 + g;
        const int rhi = rlo + 8;
        __half2* dst0 = (__half2*)g_g + (size_t)rlo * 32;
        __half2* dst1 = (__half2*)g_g + (size_t)rhi * 32;
#pragma unroll
        for (int j = 0; j < 8; j++) {
            const int hc = 4 * j + tig;
            dst0[hc] = __floats2half2_rn(c[ma][j][0], c[ma][j][1]);
            dst1[hc] = __floats2half2_rn(c[ma][j][2], c[ma][j][3]);
        }
        if (tig == 0) {
            g_tsrc[rlo] = slo; g_tdst[rlo] = dlo;
            g_tsrc[rhi] = shi; g_tdst[rhi] = dhi;
        }
    }
}

// ---------------- attn2: warp per (b,n), shfl-deduped edge scalars + elu --------
__global__ void attn2_kernel(float* __restrict__ out) {
    int gw   = (blockIdx.x * blockDim.x + threadIdx.x) >> 5;
    int lane = threadIdx.x & 31;
    if (gw >= Bz * Nn) return;
    int n = gw & (Nn - 1);
    int b = gw >> 11;
    int sub = lane & 3;
    const __half2* gb = (const __half2*)g_g + (size_t)b * Nn * 32 + lane;
    const float*   td = g_tdst + (size_t)b * Nn;
    float ti = g_tsrc[gw];
    int dg = g_deg[n];
    const int* cr = g_cols + n * MAX_DEG;
    float2 acc = {0.f, 0.f};
    float den = 0.f;
    int k = 0;
    int4 nx = *(const int4*)cr;
    for (; k + 4 <= dg; k += 4) {
        int4 mm = nx;
        if (k + 8 <= dg) nx = *(const int4*)(cr + k + 4);
        int midx = (sub == 0) ? mm.x : (sub == 1) ? mm.y : (sub == 2) ? mm.z : mm.w;
        float ev = edge_e(ti, td[midx]);
        float e0 = __shfl_sync(0xffffffffu, ev, 0);
        float e1 = __shfl_sync(0xffffffffu, ev, 1);
        float e2 = __shfl_sync(0xffffffffu, ev, 2);
        float e3 = __shfl_sync(0xffffffffu, ev, 3);
        __half2 v0 = gb[(size_t)mm.x * 32];
        __half2 v1 = gb[(size_t)mm.y * 32];
        __half2 v2 = gb[(size_t)mm.z * 32];
        __half2 v3 = gb[(size_t)mm.w * 32];
        den += (e0 + e1) + (e2 + e3);
        float2 f0 = __half22float2(v0), f1 = __half22float2(v1);
        float2 f2 = __half22float2(v2), f3 = __half22float2(v3);
        acc.x += e0 * f0.x + e1 * f1.x + e2 * f2.x + e3 * f3.x;
        acc.y += e0 * f0.y + e1 * f1.y + e2 * f2.y + e3 * f3.y;
    }
    for (; k < dg; k++) {
        int m = cr[k];
        float e = edge_e(ti, td[m]);
        float2 f = __half22float2(gb[(size_t)m * 32]);
        den += e;
        acc.x += e * f.x; acc.y += e * f.y;
    }
    float inv = 1.0f / den;
    float o0 = acc.x * inv, o1 = acc.y * inv;
    o0 = o0 > 0.f ? o0 : expm1f(o0);
    o1 = o1 > 0.f ? o1 : expm1f(o1);
    float* dst = out + (size_t)gw * NC + lane * 2;
    dst[0] = o0; dst[1] = o1;
}

// ---------------- launch -----------------------------------------------------------
extern "C" void kernel_launch(void* const* d_in, const int* in_sizes, int n_in,
                              void* d_out, int out_size) {
    const float* x   = (const float*)d_in[0];
    const float* adj = (const float*)d_in[1];
    const float* W1  = (const float*)d_in[2];
    const float* a1  = (const float*)d_in[3];
    const float* W2  = (const float*)d_in[4];
    const float* a2  = (const float*)d_in[5];
    float* out = (float*)d_out;

    const int smem1 = 4 * 128 * PADH * 2 + 512 * 4;   // 40960 + 2048 = 43008 B
    const int smem2 = 4 * 64 * PADH * 2 + 128 * 4;    // 20480 + 512  = 20992 B
    cudaFuncSetAttribute(gemm1_mma, cudaFuncAttributeMaxDynamicSharedMemorySize, smem1);
    cudaFuncSetAttribute(gemm2_mma, cudaFuncAttributeMaxDynamicSharedMemorySize, smem2);

    build_csr_kernel<<<(Nn * 32) / 256, 256>>>(adj);
    transposeW1_kernel<<<dim3(16, 2, 4), dim3(32, 8)>>>(W1);
    convertX_kernel<<<Bz * Nn * NF / 4 / 256, 256>>>(x);
    gemm1_mma<<<dim3(64, 2), 256, smem1>>>(a1);         // profiled (4th)
    attn1_kernel<<<(Bz * Nn * 32) / 256, 256>>>();
    transposeW2_kernel<<<dim3(8, 2), dim3(32, 8)>>>(W2);
    gemm2_mma<<<128, 64, smem2>>>(a2);
    attn2_kernel<<<(Bz * Nn * 32) / 256, 256>>>(out);
}

// round 16
// speedup vs baseline: 1.3469x; 1.0093x over previous
#include <cuda_runtime.h>
#include <cuda_fp16.h>
#include <cstdint>

#define Bz 4
#define Nn 2048
#define NF 512
#define ND 64
#define NH 4
#define NC 64
#define MAX_DEG 128
#define ALPHA 0.2f
#define PADH 40   // gemm2 smem row stride (halfs)
#define PADH1 72  // gemm1 smem row stride (halfs), K-step 64

// ---------------- scratch -----------------------------------------------------
__device__ __align__(16) __half g_Xh[Bz * Nn * NF];       // fp16 X          8MB
__device__ __align__(16) __half g_h [Bz * Nn * NH * ND];  // fp16 [b][n][256] 4MB
__device__ __align__(16) __half g_h1[Bz * Nn * NH * ND];  // fp16            4MB
__device__ __align__(16) __half g_g [Bz * Nn * NC];       // fp16 [b][n][64] 1MB
__device__ __align__(16) __half g_W1t[NH * ND * NF];      // fp16 [256][512]
__device__ __align__(16) __half g_W2t[NC * NH * ND];      // fp16 [64][256]
__device__ float g_ssrc[Bz * NH * Nn];
__device__ float g_sdst[Bz * NH * Nn];
__device__ float g_tsrc[Bz * Nn];
__device__ float g_tdst[Bz * Nn];
__device__ __align__(16) int g_cols[Nn * MAX_DEG];
__device__ int   g_deg[Nn];

// ---------------- helpers ------------------------------------------------------
__device__ __forceinline__ uint32_t smem_u32(const void* p) {
    uint32_t a;
    asm("{ .reg .u64 t; cvta.to.shared.u64 t, %1; cvt.u32.u64 %0, t; }" : "=r"(a) : "l"(p));
    return a;
}
__device__ __forceinline__ void cp16(uint32_t dst, const void* src) {
    asm volatile("cp.async.ca.shared.global [%0], [%1], 16;" :: "r"(dst), "l"(src));
}
#define CP_COMMIT() asm volatile("cp.async.commit_group;" ::: "memory")
#define CP_WAIT(n)  asm volatile("cp.async.wait_group %0;" :: "n"(n) : "memory")
__device__ __forceinline__ void mma16(float* c,
                                      uint32_t a0, uint32_t a1, uint32_t a2, uint32_t a3,
                                      uint32_t b0, uint32_t b1) {
    asm volatile(
        "mma.sync.aligned.m16n8k16.row.col.f32.f16.f16.f32 "
        "{%0,%1,%2,%3}, {%4,%5,%6,%7}, {%8,%9}, {%0,%1,%2,%3};"
        : "+f"(c[0]), "+f"(c[1]), "+f"(c[2]), "+f"(c[3])
        : "r"(a0), "r"(a1), "r"(a2), "r"(a3), "r"(b0), "r"(b1));
}
__device__ __forceinline__ float edge_e(float si, float sdm) {
    float z = si + sdm;
    float lr = z > 0.f ? z : ALPHA * z;
    return __expf(-lr);
}
__device__ __forceinline__ uint32_t h2u(__half2 h) {
    return *reinterpret_cast<uint32_t*>(&h);
}

// ---------------- CSR build + X->fp16 convert (fused) ----------------------------
__global__ void csr_convert_kernel(const float* __restrict__ adj,
                                   const float* __restrict__ X) {
    int gid  = blockIdx.x * blockDim.x + threadIdx.x;   // 65536 threads
    int row  = gid >> 5;
    int lane = threadIdx.x & 31;
    const float4* ar = reinterpret_cast<const float4*>(adj + (size_t)row * Nn);
    int base = 0;
    float4 v = ar[lane];
#pragma unroll 1
    for (int it = 0; it < 16; ++it) {
        float4 cur = v;
        if (it < 15) v = ar[(it + 1) * 32 + lane];
        int c0 = it * 128 + lane * 4;
        unsigned nib = (cur.x != 0.f ? 1u : 0u) | (cur.y != 0.f ? 2u : 0u)
                     | (cur.z != 0.f ? 4u : 0u) | (cur.w != 0.f ? 8u : 0u);
        int cnt = __popc(nib);
        int sc = cnt;
#pragma unroll
        for (int o = 1; o < 32; o <<= 1) {
            int t = __shfl_up_sync(0xffffffffu, sc, o);
            if (lane >= o) sc += t;
        }
        int pos = base + sc - cnt;
        int total = __shfl_sync(0xffffffffu, sc, 31);
#pragma unroll
        for (int j = 0; j < 4; j++)
            if ((nib >> j) & 1u) {
                if (pos < MAX_DEG) g_cols[row * MAX_DEG + pos] = c0 + j;
                pos++;
            }
        base += total;
    }
    if (lane == 0) g_deg[row] = base < MAX_DEG ? base : MAX_DEG;

    // X convert: 1M float4 over 65536 threads -> 16 each
#pragma unroll 1
    for (int i = 0; i < 16; ++i) {
        int idx = gid + i * 65536;
        float4 xv = ((const float4*)X)[idx];
        __half2* dst = (__half2*)g_Xh + 2 * idx;
        dst[0] = __floats2half2_rn(xv.x, xv.y);
        dst[1] = __floats2half2_rn(xv.z, xv.w);
    }
}

// ---------------- transposes (fp16 output) ---------------------------------------
__global__ void transposeW1_kernel(const float* __restrict__ W1) {
    __shared__ float t[32][33];
    int h = blockIdx.z, k0 = blockIdx.x * 32, d0 = blockIdx.y * 32;
    int tx = threadIdx.x, ty = threadIdx.y;
    const float* Wb = W1 + (size_t)h * NF * ND;
#pragma unroll
    for (int i = 0; i < 4; i++) t[ty + i * 8][tx] = Wb[(size_t)(k0 + ty + i * 8) * ND + d0 + tx];
    __syncthreads();
#pragma unroll
    for (int i = 0; i < 4; i++)
        g_W1t[(size_t)(h * 64 + d0 + ty + i * 8) * NF + k0 + tx] =
            __float2half_rn(t[tx][ty + i * 8]);
}
__global__ void transposeW2_kernel(const float* __restrict__ W2) {
    __shared__ float t[32][33];
    int k0 = blockIdx.x * 32, c0 = blockIdx.y * 32;
    int tx = threadIdx.x, ty = threadIdx.y;
#pragma unroll
    for (int i = 0; i < 4; i++) t[ty + i * 8][tx] = W2[(size_t)(k0 + ty + i * 8) * NC + c0 + tx];
    __syncthreads();
#pragma unroll
    for (int i = 0; i < 4; i++)
        g_W2t[(size_t)(c0 + ty + i * 8) * (NH * ND) + k0 + tx] =
            __float2half_rn(t[tx][ty + i * 8]);
}

// ---------------- gemm1: fp16 m16n8k16, K-step 64, fused s dots ------------------
// CTA 128x128, grid (64, 2). 8 warps = 4M x 2N, warp tile 32x64. 8 K-iterations.
__global__ void __launch_bounds__(256) gemm1_mma(const float* __restrict__ a1) {
    extern __shared__ __half smh[];
    __half* sA  = smh;                      // [2][128][PADH1]
    __half* sB  = smh + 2 * 128 * PADH1;    // [2][128][PADH1]
    float*  sa1 = (float*)(smh + 4 * 128 * PADH1);  // [512]
    const int tid = threadIdx.x, lane = tid & 31, warp = tid >> 5;
    const int wm = warp & 3, wn = warp >> 2;
    const int g = lane >> 2, tig = lane & 3;
    const int row0 = blockIdx.x * 128, col0 = blockIdx.y * 128;
    sa1[tid] = a1[tid]; sa1[tid + 256] = a1[tid + 256];

    // loaders: 2 threads/row, 32 halfs (4 cp16) each; kt covers 64 halfs
    const __half* gA = g_Xh  + (size_t)(row0 + (tid >> 1)) * NF + (tid & 1) * 32;
    const __half* gB = g_W1t + (size_t)(col0 + (tid >> 1)) * NF + (tid & 1) * 32;
    const uint32_t dA = smem_u32(&sA[(tid >> 1) * PADH1 + (tid & 1) * 32]);
    const uint32_t dB = smem_u32(&sB[(tid >> 1) * PADH1 + (tid & 1) * 32]);
    const uint32_t STRIDE = 128 * PADH1 * 2;   // bytes per buffer

#define ISSUE(buf, kt)                                                 \
    do {                                                               \
        _Pragma("unroll")                                              \
        for (int i = 0; i < 4; i++)                                    \
            cp16(dA + (buf) * STRIDE + 16 * i, gA + (kt) * 64 + 8 * i);\
        _Pragma("unroll")                                              \
        for (int i = 0; i < 4; i++)                                    \
            cp16(dB + (buf) * STRIDE + 16 * i, gB + (kt) * 64 + 8 * i);\
        CP_COMMIT();                                                   \
    } while (0)

    float c[2][8][4];
#pragma unroll
    for (int i = 0; i < 2; i++)
#pragma unroll
        for (int j = 0; j < 8; j++)
#pragma unroll
            for (int q = 0; q < 4; q++) c[i][j][q] = 0.f;

    ISSUE(0, 0);
#pragma unroll 1
    for (int kt = 0; kt < 8; ++kt) {
        const int buf = kt & 1;
        if (kt < 7) { ISSUE(buf ^ 1, kt + 1); CP_WAIT(1); }
        else        { CP_WAIT(0); }
        __syncthreads();
        const __half* A0 = sA + buf * 128 * PADH1;
        const __half* B0 = sB + buf * 128 * PADH1;
#pragma unroll
        for (int ks = 0; ks < 4; ++ks) {                // 4 x k16 per kt
            const int kb = ks * 16 + 2 * tig;
            uint32_t af[2][4];
#pragma unroll
            for (int ma = 0; ma < 2; ma++) {
                const __half* ar0 = A0 + (wm * 32 + ma * 16 + g) * PADH1 + kb;
                af[ma][0] = *(const uint32_t*)(ar0);
                af[ma][1] = *(const uint32_t*)(ar0 + 8 * PADH1);
                af[ma][2] = *(const uint32_t*)(ar0 + 8);
                af[ma][3] = *(const uint32_t*)(ar0 + 8 * PADH1 + 8);
            }
#pragma unroll
            for (int j = 0; j < 8; j++) {
                const __half* br0 = B0 + (wn * 64 + 8 * j + g) * PADH1 + kb;
                uint32_t b0 = *(const uint32_t*)(br0);
                uint32_t b1 = *(const uint32_t*)(br0 + 8);
                mma16(c[0][j], af[0][0], af[0][1], af[0][2], af[0][3], b0, b1);
                mma16(c[1][j], af[1][0], af[1][1], af[1][2], af[1][3], b0, b1);
            }
        }
        __syncthreads();
    }
#undef ISSUE

    // epilogue: store h rows (fp16) + fused s_src/s_dst (warp's 64 cols == one head)
    const int head = blockIdx.y * 2 + wn;
    const float* ahs = sa1 + head * 128;
#pragma unroll
    for (int ma = 0; ma < 2; ma++) {
        float slo = 0.f, dlo = 0.f, shi = 0.f, dhi = 0.f;
#pragma unroll
        for (int j = 0; j < 8; j++) {
            const int col = 8 * j + 2 * tig;
            float w0 = ahs[col], w1 = ahs[col + 1];
            float u0 = ahs[64 + col], u1 = ahs[64 + col + 1];
            slo += c[ma][j][0] * w0 + c[ma][j][1] * w1;
            dlo += c[ma][j][0] * u0 + c[ma][j][1] * u1;
            shi += c[ma][j][2] * w0 + c[ma][j][3] * w1;
            dhi += c[ma][j][2] * u0 + c[ma][j][3] * u1;
        }
#pragma unroll
        for (int o = 1; o < 4; o <<= 1) {
            slo += __shfl_xor_sync(0xffffffffu, slo, o);
            dlo += __shfl_xor_sync(0xffffffffu, dlo, o);
            shi += __shfl_xor_sync(0xffffffffu, shi, o);
            dhi += __shfl_xor_sync(0xffffffffu, dhi, o);
        }
        const int rlo = row0 + wm * 32 + ma * 16 + g;
        const int rhi = rlo + 8;
        __half2* dst0 = (__half2*)g_h + ((size_t)rlo * 256 + head * 64) / 2;
        __half2* dst1 = (__half2*)g_h + ((size_t)rhi * 256 + head * 64) / 2;
#pragma unroll
        for (int j = 0; j < 8; j++) {
            const int hc = 4 * j + tig;
            dst0[hc] = __floats2half2_rn(c[ma][j][0], c[ma][j][1]);
            dst1[hc] = __floats2half2_rn(c[ma][j][2], c[ma][j][3]);
        }
        if (tig == 0) {
            int b0i = rlo >> 11, n0i = rlo & (Nn - 1);
            int b1i = rhi >> 11, n1i = rhi & (Nn - 1);
            g_ssrc[(b0i * NH + head) * Nn + n0i] = slo;
            g_sdst[(b0i * NH + head) * Nn + n0i] = dlo;
            g_ssrc[(b1i * NH + head) * Nn + n1i] = shi;
            g_sdst[(b1i * NH + head) * Nn + n1i] = dhi;
        }
    }
}

// ---------------- attn1: warp per (b,n), fp16 gather; h1 stored fp16 -------------
__global__ void attn1_kernel() {
    int gw   = (blockIdx.x * blockDim.x + threadIdx.x) >> 5;   // b*Nn + n
    int lane = threadIdx.x & 31;
    if (gw >= Bz * Nn) return;
    int n = gw & (Nn - 1), b = gw >> 11;
    int head = lane >> 3;
    const uint4* hb = reinterpret_cast<const uint4*>(
        g_h + (size_t)b * Nn * 256 + lane * 8);
    const float* sdp = g_sdst + (size_t)(b * NH + head) * Nn;
    float si = g_ssrc[(size_t)(b * NH + head) * Nn + n];
    int dg = g_deg[n];
    const int* cr = g_cols + n * MAX_DEG;
    float acc[8] = {};
    float den = 0.f;
    int k = 0;
    int4 nx = *(const int4*)cr;
    for (; k + 4 <= dg; k += 4) {
        int4 mm = nx;
        if (k + 8 <= dg) nx = *(const int4*)(cr + k + 4);
        float d0 = sdp[mm.x], d1 = sdp[mm.y], d2 = sdp[mm.z], d3 = sdp[mm.w];
        uint4 r0 = hb[(size_t)mm.x * 32];
        uint4 r1 = hb[(size_t)mm.y * 32];
        uint4 r2 = hb[(size_t)mm.z * 32];
        uint4 r3 = hb[(size_t)mm.w * 32];
        float e0 = edge_e(si, d0), e1 = edge_e(si, d1);
        float e2 = edge_e(si, d2), e3 = edge_e(si, d3);
        den += (e0 + e1) + (e2 + e3);
        const uint32_t* w0 = &r0.x; const uint32_t* w1 = &r1.x;
        const uint32_t* w2 = &r2.x; const uint32_t* w3 = &r3.x;
#pragma unroll
        for (int p = 0; p < 4; p++) {
            float2 f0 = __half22float2(*(const __half2*)&w0[p]);
            float2 f1 = __half22float2(*(const __half2*)&w1[p]);
            float2 f2 = __half22float2(*(const __half2*)&w2[p]);
            float2 f3 = __half22float2(*(const __half2*)&w3[p]);
            acc[2 * p]     += e0 * f0.x + e1 * f1.x + e2 * f2.x + e3 * f3.x;
            acc[2 * p + 1] += e0 * f0.y + e1 * f1.y + e2 * f2.y + e3 * f3.y;
        }
    }
    for (; k < dg; k++) {
        int m = cr[k];
        float e = edge_e(si, sdp[m]);
        uint4 r = hb[(size_t)m * 32];
        const uint32_t* w = &r.x;
        den += e;
#pragma unroll
        for (int p = 0; p < 4; p++) {
            float2 f = __half22float2(*(const __half2*)&w[p]);
            acc[2 * p]     += e * f.x;
            acc[2 * p + 1] += e * f.y;
        }
    }
    float inv = 1.0f / den;
    float o[8];
#pragma unroll
    for (int j = 0; j < 8; j++) {
        o[j] = acc[j] * inv;
        o[j] = o[j] > 0.f ? o[j] : expm1f(o[j]);
    }
    uint4 u;
    u.x = h2u(__floats2half2_rn(o[0], o[1]));
    u.y = h2u(__floats2half2_rn(o[2], o[3]));
    u.z = h2u(__floats2half2_rn(o[4], o[5]));
    u.w = h2u(__floats2half2_rn(o[6], o[7]));
    *(uint4*)(g_h1 + (size_t)gw * 256 + lane * 8) = u;
}

// ---------------- gemm2: g = h1 @ W2t^T, fp16 m16n8k16, fused t dots -------------
__global__ void __launch_bounds__(64, 6) gemm2_mma(const float* __restrict__ a2) {
    extern __shared__ __half smh[];
    __half* sA  = smh;                    // [2][64][PADH]
    __half* sB  = smh + 2 * 64 * PADH;    // [2][64][PADH]
    float*  sa2 = (float*)(smh + 4 * 64 * PADH);  // [128]
    const int tid = threadIdx.x, lane = tid & 31, warp = tid >> 5;
    const int g = lane >> 2, tig = lane & 3;
    const int row0 = blockIdx.x * 64;
    const int K = NH * ND;  // 256
    sa2[tid] = a2[tid]; sa2[tid + 64] = a2[tid + 64];

    const __half* gA = g_h1  + (size_t)(row0 + tid) * K;
    const __half* gB = g_W2t + (size_t)tid * K;
    const uint32_t dA = smem_u32(&sA[tid * PADH]);
    const uint32_t dB = smem_u32(&sB[tid * PADH]);
    const uint32_t STRIDE = 64 * PADH * 2;

#define ISSUE2(buf, kt)                                                \
    do {                                                               \
        _Pragma("unroll")                                              \
        for (int i = 0; i < 4; i++)                                    \
            cp16(dA + (buf) * STRIDE + 16 * i, gA + (kt) * 32 + 8 * i);\
        _Pragma("unroll")                                              \
        for (int i = 0; i < 4; i++)                                    \
            cp16(dB + (buf) * STRIDE + 16 * i, gB + (kt) * 32 + 8 * i);\
        CP_COMMIT();                                                   \
    } while (0)

    float c[2][8][4];
#pragma unroll
    for (int i = 0; i < 2; i++)
#pragma unroll
        for (int j = 0; j < 8; j++)
#pragma unroll
            for (int q = 0; q < 4; q++) c[i][j][q] = 0.f;

    ISSUE2(0, 0);
#pragma unroll 1
    for (int kt = 0; kt < 8; ++kt) {
        const int buf = kt & 1;
        if (kt < 7) { ISSUE2(buf ^ 1, kt + 1); CP_WAIT(1); }
        else        { CP_WAIT(0); }
        __syncthreads();
        const __half* A0 = sA + buf * 64 * PADH;
        const __half* B0 = sB + buf * 64 * PADH;
#pragma unroll
        for (int ks = 0; ks < 2; ++ks) {
            const int kb = ks * 16 + 2 * tig;
            uint32_t af[2][4];
#pragma unroll
            for (int ma = 0; ma < 2; ma++) {
                const __half* ar0 = A0 + (warp * 32 + ma * 16 + g) * PADH + kb;
                af[ma][0] = *(const uint32_t*)(ar0);
                af[ma][1] = *(const uint32_t*)(ar0 + 8 * PADH);
                af[ma][2] = *(const uint32_t*)(ar0 + 8);
                af[ma][3] = *(const uint32_t*)(ar0 + 8 * PADH + 8);
            }
#pragma unroll
            for (int j = 0; j < 8; j++) {
                const __half* br0 = B0 + (8 * j + g) * PADH + kb;
                uint32_t b0 = *(const uint32_t*)(br0);
                uint32_t b1 = *(const uint32_t*)(br0 + 8);
                mma16(c[0][j], af[0][0], af[0][1], af[0][2], af[0][3], b0, b1);
                mma16(c[1][j], af[1][0], af[1][1], af[1][2], af[1][3], b0, b1);
            }
        }
        __syncthreads();
    }
#undef ISSUE2

#pragma unroll
    for (int ma = 0; ma < 2; ma++) {
        float slo = 0.f, dlo = 0.f, shi = 0.f, dhi = 0.f;
#pragma unroll
        for (int j = 0; j < 8; j++) {
            const int col = 8 * j + 2 * tig;
            float w0 = sa2[col], w1 = sa2[col + 1];
            float u0 = sa2[64 + col], u1 = sa2[64 + col + 1];
            slo += c[ma][j][0] * w0 + c[ma][j][1] * w1;
            dlo += c[ma][j][0] * u0 + c[ma][j][1] * u1;
            shi += c[ma][j][2] * w0 + c[ma][j][3] * w1;
            dhi += c[ma][j][2] * u0 + c[ma][j][3] * u1;
        }
#pragma unroll
        for (int o = 1; o < 4; o <<= 1) {
            slo += __shfl_xor_sync(0xffffffffu, slo, o);
            dlo += __shfl_xor_sync(0xffffffffu, dlo, o);
            shi += __shfl_xor_sync(0xffffffffu, shi, o);
            dhi += __shfl_xor_sync(0xffffffffu, dhi, o);
        }
        const int rlo = row0 + warp * 32 + ma * 16 + g;
        const int rhi = rlo + 8;
        __half2* dst0 = (__half2*)g_g + (size_t)rlo * 32;
        __half2* dst1 = (__half2*)g_g + (size_t)rhi * 32;
#pragma unroll
        for (int j = 0; j < 8; j++) {
            const int hc = 4 * j + tig;
            dst0[hc] = __floats2half2_rn(c[ma][j][0], c[ma][j][1]);
            dst1[hc] = __floats2half2_rn(c[ma][j][2], c[ma][j][3]);
        }
        if (tig == 0) {
            g_tsrc[rlo] = slo; g_tdst[rlo] = dlo;
            g_tsrc[rhi] = shi; g_tdst[rhi] = dhi;
        }
    }
}

// ---------------- attn2: warp per (b,n), shfl-deduped edge scalars + elu --------
__global__ void attn2_kernel(float* __restrict__ out) {
    int gw   = (blockIdx.x * blockDim.x + threadIdx.x) >> 5;
    int lane = threadIdx.x & 31;
    if (gw >= Bz * Nn) return;
    int n = gw & (Nn - 1);
    int b = gw >> 11;
    int sub = lane & 3;
    const __half2* gb = (const __half2*)g_g + (size_t)b * Nn * 32 + lane;
    const float*   td = g_tdst + (size_t)b * Nn;
    float ti = g_tsrc[gw];
    int dg = g_deg[n];
    const int* cr = g_cols + n * MAX_DEG;
    float2 acc = {0.f, 0.f};
    float den = 0.f;
    int k = 0;
    int4 nx = *(const int4*)cr;
    for (; k + 4 <= dg; k += 4) {
        int4 mm = nx;
        if (k + 8 <= dg) nx = *(const int4*)(cr + k + 4);
        int midx = (sub == 0) ? mm.x : (sub == 1) ? mm.y : (sub == 2) ? mm.z : mm.w;
        float ev = edge_e(ti, td[midx]);
        float e0 = __shfl_sync(0xffffffffu, ev, 0);
        float e1 = __shfl_sync(0xffffffffu, ev, 1);
        float e2 = __shfl_sync(0xffffffffu, ev, 2);
        float e3 = __shfl_sync(0xffffffffu, ev, 3);
        __half2 v0 = gb[(size_t)mm.x * 32];
        __half2 v1 = gb[(size_t)mm.y * 32];
        __half2 v2 = gb[(size_t)mm.z * 32];
        __half2 v3 = gb[(size_t)mm.w * 32];
        den += (e0 + e1) + (e2 + e3);
        float2 f0 = __half22float2(v0), f1 = __half22float2(v1);
        float2 f2 = __half22float2(v2), f3 = __half22float2(v3);
        acc.x += e0 * f0.x + e1 * f1.x + e2 * f2.x + e3 * f3.x;
        acc.y += e0 * f0.y + e1 * f1.y + e2 * f2.y + e3 * f3.y;
    }
    for (; k < dg; k++) {
        int m = cr[k];
        float e = edge_e(ti, td[m]);
        float2 f = __half22float2(gb[(size_t)m * 32]);
        den += e;
        acc.x += e * f.x; acc.y += e * f.y;
    }
    float inv = 1.0f / den;
    float o0 = acc.x * inv, o1 = acc.y * inv;
    o0 = o0 > 0.f ? o0 : expm1f(o0);
    o1 = o1 > 0.f ? o1 : expm1f(o1);
    float* dst = out + (size_t)gw * NC + lane * 2;
    dst[0] = o0; dst[1] = o1;
}

// ---------------- launch -----------------------------------------------------------
extern "C" void kernel_launch(void* const* d_in, const int* in_sizes, int n_in,
                              void* d_out, int out_size) {
    const float* x   = (const float*)d_in[0];
    const float* adj = (const float*)d_in[1];
    const float* W1  = (const float*)d_in[2];
    const float* a1  = (const float*)d_in[3];
    const float* W2  = (const float*)d_in[4];
    const float* a2  = (const float*)d_in[5];
    float* out = (float*)d_out;

    const int smem1 = 4 * 128 * PADH1 * 2 + 512 * 4;  // 73728 + 2048 = 75776 B
    const int smem2 = 4 * 64 * PADH * 2 + 128 * 4;    // 20480 + 512  = 20992 B
    cudaFuncSetAttribute(gemm1_mma, cudaFuncAttributeMaxDynamicSharedMemorySize, smem1);
    cudaFuncSetAttribute(gemm2_mma, cudaFuncAttributeMaxDynamicSharedMemorySize, smem2);

    csr_convert_kernel<<<(Nn * 32) / 256, 256>>>(adj, x);
    transposeW1_kernel<<<dim3(16, 2, 4), dim3(32, 8)>>>(W1);
    transposeW2_kernel<<<dim3(8, 2), dim3(32, 8)>>>(W2);
    gemm1_mma<<<dim3(64, 2), 256, smem1>>>(a1);         // profiled (4th)
    attn1_kernel<<<(Bz * Nn * 32) / 256, 256>>>();
    gemm2_mma<<<128, 64, smem2>>>(a2);
    attn2_kernel<<<(Bz * Nn * 32) / 256, 256>>>(out);
}

// round 17
// speedup vs baseline: 1.3710x; 1.0179x over previous
#include <cuda_runtime.h>
#include <cuda_fp16.h>
#include <cstdint>

#define Bz 4
#define Nn 2048
#define NF 512
#define ND 64
#define NH 4
#define NC 64
#define MAX_DEG 128
#define ALPHA 0.2f
#define PADH 40   // gemm2 smem row stride (halfs)
#define PADH1 72  // gemm1 smem row stride (halfs), K-step 64

// ---------------- scratch -----------------------------------------------------
__device__ __align__(16) __half g_Xh[Bz * Nn * NF];       // fp16 X          8MB
__device__ __align__(16) __half g_h [Bz * Nn * NH * ND];  // fp16 [b][n][256] 4MB
__device__ __align__(16) __half g_h1[Bz * Nn * NH * ND];  // fp16            4MB
__device__ __align__(16) __half g_g [Bz * Nn * NC];       // fp16 [b][n][64] 1MB
__device__ __align__(16) __half g_W1t[NH * ND * NF];      // fp16 [256][512]
__device__ __align__(16) __half g_W2t[NC * NH * ND];      // fp16 [64][256]
__device__ float g_ssrc[Bz * NH * Nn];
__device__ float g_sdst[Bz * NH * Nn];
__device__ float g_tsrc[Bz * Nn];
__device__ float g_tdst[Bz * Nn];
__device__ __align__(16) int g_cols[Nn * MAX_DEG];
__device__ int   g_deg[Nn];

// ---------------- helpers ------------------------------------------------------
__device__ __forceinline__ uint32_t smem_u32(const void* p) {
    uint32_t a;
    asm("{ .reg .u64 t; cvta.to.shared.u64 t, %1; cvt.u32.u64 %0, t; }" : "=r"(a) : "l"(p));
    return a;
}
__device__ __forceinline__ void cp16(uint32_t dst, const void* src) {
    asm volatile("cp.async.ca.shared.global [%0], [%1], 16;" :: "r"(dst), "l"(src));
}
#define CP_COMMIT() asm volatile("cp.async.commit_group;" ::: "memory")
#define CP_WAIT(n)  asm volatile("cp.async.wait_group %0;" :: "n"(n) : "memory")
__device__ __forceinline__ void mma16(float* c,
                                      uint32_t a0, uint32_t a1, uint32_t a2, uint32_t a3,
                                      uint32_t b0, uint32_t b1) {
    asm volatile(
        "mma.sync.aligned.m16n8k16.row.col.f32.f16.f16.f32 "
        "{%0,%1,%2,%3}, {%4,%5,%6,%7}, {%8,%9}, {%0,%1,%2,%3};"
        : "+f"(c[0]), "+f"(c[1]), "+f"(c[2]), "+f"(c[3])
        : "r"(a0), "r"(a1), "r"(a2), "r"(a3), "r"(b0), "r"(b1));
}
__device__ __forceinline__ float edge_e(float si, float sdm) {
    float z = si + sdm;
    float lr = z > 0.f ? z : ALPHA * z;
    return __expf(-lr);
}
__device__ __forceinline__ uint32_t h2u(__half2 h) {
    return *reinterpret_cast<uint32_t*>(&h);
}

// ---------------- CSR build + X->fp16 convert (fused) ----------------------------
__global__ void csr_convert_kernel(const float* __restrict__ adj,
                                   const float* __restrict__ X) {
    int gid  = blockIdx.x * blockDim.x + threadIdx.x;   // 65536 threads
    int row  = gid >> 5;
    int lane = threadIdx.x & 31;
    const float4* ar = reinterpret_cast<const float4*>(adj + (size_t)row * Nn);
    int base = 0;
    float4 v = ar[lane];
#pragma unroll 1
    for (int it = 0; it < 16; ++it) {
        float4 cur = v;
        if (it < 15) v = ar[(it + 1) * 32 + lane];
        int c0 = it * 128 + lane * 4;
        unsigned nib = (cur.x != 0.f ? 1u : 0u) | (cur.y != 0.f ? 2u : 0u)
                     | (cur.z != 0.f ? 4u : 0u) | (cur.w != 0.f ? 8u : 0u);
        int cnt = __popc(nib);
        int sc = cnt;
#pragma unroll
        for (int o = 1; o < 32; o <<= 1) {
            int t = __shfl_up_sync(0xffffffffu, sc, o);
            if (lane >= o) sc += t;
        }
        int pos = base + sc - cnt;
        int total = __shfl_sync(0xffffffffu, sc, 31);
#pragma unroll
        for (int j = 0; j < 4; j++)
            if ((nib >> j) & 1u) {
                if (pos < MAX_DEG) g_cols[row * MAX_DEG + pos] = c0 + j;
                pos++;
            }
        base += total;
    }
    if (lane == 0) g_deg[row] = base < MAX_DEG ? base : MAX_DEG;

    // X convert: 1M float4 over 65536 threads -> 16 each
#pragma unroll 1
    for (int i = 0; i < 16; ++i) {
        int idx = gid + i * 65536;
        float4 xv = ((const float4*)X)[idx];
        __half2* dst = (__half2*)g_Xh + 2 * idx;
        dst[0] = __floats2half2_rn(xv.x, xv.y);
        dst[1] = __floats2half2_rn(xv.z, xv.w);
    }
}

// ---------------- transposes (fp16 output) ---------------------------------------
__global__ void transposeW1_kernel(const float* __restrict__ W1) {
    __shared__ float t[32][33];
    int h = blockIdx.z, k0 = blockIdx.x * 32, d0 = blockIdx.y * 32;
    int tx = threadIdx.x, ty = threadIdx.y;
    const float* Wb = W1 + (size_t)h * NF * ND;
#pragma unroll
    for (int i = 0; i < 4; i++) t[ty + i * 8][tx] = Wb[(size_t)(k0 + ty + i * 8) * ND + d0 + tx];
    __syncthreads();
#pragma unroll
    for (int i = 0; i < 4; i++)
        g_W1t[(size_t)(h * 64 + d0 + ty + i * 8) * NF + k0 + tx] =
            __float2half_rn(t[tx][ty + i * 8]);
}
__global__ void transposeW2_kernel(const float* __restrict__ W2) {
    __shared__ float t[32][33];
    int k0 = blockIdx.x * 32, c0 = blockIdx.y * 32;
    int tx = threadIdx.x, ty = threadIdx.y;
#pragma unroll
    for (int i = 0; i < 4; i++) t[ty + i * 8][tx] = W2[(size_t)(k0 + ty + i * 8) * NC + c0 + tx];
    __syncthreads();
#pragma unroll
    for (int i = 0; i < 4; i++)
        g_W2t[(size_t)(c0 + ty + i * 8) * (NH * ND) + k0 + tx] =
            __float2half_rn(t[tx][ty + i * 8]);
}

// ---------------- gemm1: fp16 m16n8k16, K-step 64, fused s dots ------------------
// CTA 128x128, grid (64, 2). 8 warps = 4M x 2N, warp tile 32x64. 8 K-iterations.
__global__ void __launch_bounds__(256) gemm1_mma(const float* __restrict__ a1) {
    extern __shared__ __half smh[];
    __half* sA  = smh;                      // [2][128][PADH1]
    __half* sB  = smh + 2 * 128 * PADH1;    // [2][128][PADH1]
    float*  sa1 = (float*)(smh + 4 * 128 * PADH1);  // [512]
    const int tid = threadIdx.x, lane = tid & 31, warp = tid >> 5;
    const int wm = warp & 3, wn = warp >> 2;
    const int g = lane >> 2, tig = lane & 3;
    const int row0 = blockIdx.x * 128, col0 = blockIdx.y * 128;
    sa1[tid] = a1[tid]; sa1[tid + 256] = a1[tid + 256];

    const __half* gA = g_Xh  + (size_t)(row0 + (tid >> 1)) * NF + (tid & 1) * 32;
    const __half* gB = g_W1t + (size_t)(col0 + (tid >> 1)) * NF + (tid & 1) * 32;
    const uint32_t dA = smem_u32(&sA[(tid >> 1) * PADH1 + (tid & 1) * 32]);
    const uint32_t dB = smem_u32(&sB[(tid >> 1) * PADH1 + (tid & 1) * 32]);
    const uint32_t STRIDE = 128 * PADH1 * 2;

#define ISSUE(buf, kt)                                                 \
    do {                                                               \
        _Pragma("unroll")                                              \
        for (int i = 0; i < 4; i++)                                    \
            cp16(dA + (buf) * STRIDE + 16 * i, gA + (kt) * 64 + 8 * i);\
        _Pragma("unroll")                                              \
        for (int i = 0; i < 4; i++)                                    \
            cp16(dB + (buf) * STRIDE + 16 * i, gB + (kt) * 64 + 8 * i);\
        CP_COMMIT();                                                   \
    } while (0)

    float c[2][8][4];
#pragma unroll
    for (int i = 0; i < 2; i++)
#pragma unroll
        for (int j = 0; j < 8; j++)
#pragma unroll
            for (int q = 0; q < 4; q++) c[i][j][q] = 0.f;

    ISSUE(0, 0);
#pragma unroll 1
    for (int kt = 0; kt < 8; ++kt) {
        const int buf = kt & 1;
        if (kt < 7) { ISSUE(buf ^ 1, kt + 1); CP_WAIT(1); }
        else        { CP_WAIT(0); }
        __syncthreads();
        const __half* A0 = sA + buf * 128 * PADH1;
        const __half* B0 = sB + buf * 128 * PADH1;
#pragma unroll
        for (int ks = 0; ks < 4; ++ks) {
            const int kb = ks * 16 + 2 * tig;
            uint32_t af[2][4];
#pragma unroll
            for (int ma = 0; ma < 2; ma++) {
                const __half* ar0 = A0 + (wm * 32 + ma * 16 + g) * PADH1 + kb;
                af[ma][0] = *(const uint32_t*)(ar0);
                af[ma][1] = *(const uint32_t*)(ar0 + 8 * PADH1);
                af[ma][2] = *(const uint32_t*)(ar0 + 8);
                af[ma][3] = *(const uint32_t*)(ar0 + 8 * PADH1 + 8);
            }
#pragma unroll
            for (int j = 0; j < 8; j++) {
                const __half* br0 = B0 + (wn * 64 + 8 * j + g) * PADH1 + kb;
                uint32_t b0 = *(const uint32_t*)(br0);
                uint32_t b1 = *(const uint32_t*)(br0 + 8);
                mma16(c[0][j], af[0][0], af[0][1], af[0][2], af[0][3], b0, b1);
                mma16(c[1][j], af[1][0], af[1][1], af[1][2], af[1][3], b0, b1);
            }
        }
        __syncthreads();
    }
#undef ISSUE

    const int head = blockIdx.y * 2 + wn;
    const float* ahs = sa1 + head * 128;
#pragma unroll
    for (int ma = 0; ma < 2; ma++) {
        float slo = 0.f, dlo = 0.f, shi = 0.f, dhi = 0.f;
#pragma unroll
        for (int j = 0; j < 8; j++) {
            const int col = 8 * j + 2 * tig;
            float w0 = ahs[col], w1 = ahs[col + 1];
            float u0 = ahs[64 + col], u1 = ahs[64 + col + 1];
            slo += c[ma][j][0] * w0 + c[ma][j][1] * w1;
            dlo += c[ma][j][0] * u0 + c[ma][j][1] * u1;
            shi += c[ma][j][2] * w0 + c[ma][j][3] * w1;
            dhi += c[ma][j][2] * u0 + c[ma][j][3] * u1;
        }
#pragma unroll
        for (int o = 1; o < 4; o <<= 1) {
            slo += __shfl_xor_sync(0xffffffffu, slo, o);
            dlo += __shfl_xor_sync(0xffffffffu, dlo, o);
            shi += __shfl_xor_sync(0xffffffffu, shi, o);
            dhi += __shfl_xor_sync(0xffffffffu, dhi, o);
        }
        const int rlo = row0 + wm * 32 + ma * 16 + g;
        const int rhi = rlo + 8;
        __half2* dst0 = (__half2*)g_h + ((size_t)rlo * 256 + head * 64) / 2;
        __half2* dst1 = (__half2*)g_h + ((size_t)rhi * 256 + head * 64) / 2;
#pragma unroll
        for (int j = 0; j < 8; j++) {
            const int hc = 4 * j + tig;
            dst0[hc] = __floats2half2_rn(c[ma][j][0], c[ma][j][1]);
            dst1[hc] = __floats2half2_rn(c[ma][j][2], c[ma][j][3]);
        }
        if (tig == 0) {
            int b0i = rlo >> 11, n0i = rlo & (Nn - 1);
            int b1i = rhi >> 11, n1i = rhi & (Nn - 1);
            g_ssrc[(b0i * NH + head) * Nn + n0i] = slo;
            g_sdst[(b0i * NH + head) * Nn + n0i] = dlo;
            g_ssrc[(b1i * NH + head) * Nn + n1i] = shi;
            g_sdst[(b1i * NH + head) * Nn + n1i] = dhi;
        }
    }
}

// ---------------- attn1: warp per (b,n), fp16-pair accumulation ------------------
__global__ void attn1_kernel() {
    int gw   = (blockIdx.x * blockDim.x + threadIdx.x) >> 5;   // b*Nn + n
    int lane = threadIdx.x & 31;
    if (gw >= Bz * Nn) return;
    int n = gw & (Nn - 1), b = gw >> 11;
    int head = lane >> 3;
    const uint4* hb = reinterpret_cast<const uint4*>(
        g_h + (size_t)b * Nn * 256 + lane * 8);
    const float* sdp = g_sdst + (size_t)(b * NH + head) * Nn;
    float si = g_ssrc[(size_t)(b * NH + head) * Nn + n];
    int dg = g_deg[n];
    const int* cr = g_cols + n * MAX_DEG;
    float acc[8] = {};
    float den = 0.f;
    int k = 0;
    int4 nx = *(const int4*)cr;
    for (; k + 4 <= dg; k += 4) {
        int4 mm = nx;
        if (k + 8 <= dg) nx = *(const int4*)(cr + k + 4);
        float d0 = sdp[mm.x], d1 = sdp[mm.y], d2 = sdp[mm.z], d3 = sdp[mm.w];
        uint4 r0 = hb[(size_t)mm.x * 32];
        uint4 r1 = hb[(size_t)mm.y * 32];
        uint4 r2 = hb[(size_t)mm.z * 32];
        uint4 r3 = hb[(size_t)mm.w * 32];
        float e0 = edge_e(si, d0), e1 = edge_e(si, d1);
        float e2 = edge_e(si, d2), e3 = edge_e(si, d3);
        den += (e0 + e1) + (e2 + e3);
        __half2 e0h = __float2half2_rn(e0), e1h = __float2half2_rn(e1);
        __half2 e2h = __float2half2_rn(e2), e3h = __float2half2_rn(e3);
        const uint32_t* w0 = &r0.x; const uint32_t* w1 = &r1.x;
        const uint32_t* w2 = &r2.x; const uint32_t* w3 = &r3.x;
#pragma unroll
        for (int p = 0; p < 4; p++) {
            // 4-edge partial product-sum in half2, fold into fp32 accs
            __half2 prod = __hmul2(*(const __half2*)&w0[p], e0h);
            prod = __hfma2(*(const __half2*)&w1[p], e1h, prod);
            prod = __hfma2(*(const __half2*)&w2[p], e2h, prod);
            prod = __hfma2(*(const __half2*)&w3[p], e3h, prod);
            float2 f = __half22float2(prod);
            acc[2 * p]     += f.x;
            acc[2 * p + 1] += f.y;
        }
    }
    for (; k < dg; k++) {
        int m = cr[k];
        float e = edge_e(si, sdp[m]);
        uint4 r = hb[(size_t)m * 32];
        const uint32_t* w = &r.x;
        den += e;
#pragma unroll
        for (int p = 0; p < 4; p++) {
            float2 f = __half22float2(*(const __half2*)&w[p]);
            acc[2 * p]     += e * f.x;
            acc[2 * p + 1] += e * f.y;
        }
    }
    float inv = 1.0f / den;
    float o[8];
#pragma unroll
    for (int j = 0; j < 8; j++) {
        o[j] = acc[j] * inv;
        o[j] = o[j] > 0.f ? o[j] : expm1f(o[j]);
    }
    uint4 u;
    u.x = h2u(__floats2half2_rn(o[0], o[1]));
    u.y = h2u(__floats2half2_rn(o[2], o[3]));
    u.z = h2u(__floats2half2_rn(o[4], o[5]));
    u.w = h2u(__floats2half2_rn(o[6], o[7]));
    *(uint4*)(g_h1 + (size_t)gw * 256 + lane * 8) = u;
}

// ---------------- gemm2: g = h1 @ W2t^T, fp16 m16n8k16, fused t dots -------------
__global__ void __launch_bounds__(64, 6) gemm2_mma(const float* __restrict__ a2) {
    extern __shared__ __half smh[];
    __half* sA  = smh;                    // [2][64][PADH]
    __half* sB  = smh + 2 * 64 * PADH;    // [2][64][PADH]
    float*  sa2 = (float*)(smh + 4 * 64 * PADH);  // [128]
    const int tid = threadIdx.x, lane = tid & 31, warp = tid >> 5;
    const int g = lane >> 2, tig = lane & 3;
    const int row0 = blockIdx.x * 64;
    const int K = NH * ND;  // 256
    sa2[tid] = a2[tid]; sa2[tid + 64] = a2[tid + 64];

    const __half* gA = g_h1  + (size_t)(row0 + tid) * K;
    const __half* gB = g_W2t + (size_t)tid * K;
    const uint32_t dA = smem_u32(&sA[tid * PADH]);
    const uint32_t dB = smem_u32(&sB[tid * PADH]);
    const uint32_t STRIDE = 64 * PADH * 2;

#define ISSUE2(buf, kt)                                                \
    do {                                                               \
        _Pragma("unroll")                                              \
        for (int i = 0; i < 4; i++)                                    \
            cp16(dA + (buf) * STRIDE + 16 * i, gA + (kt) * 32 + 8 * i);\
        _Pragma("unroll")                                              \
        for (int i = 0; i < 4; i++)                                    \
            cp16(dB + (buf) * STRIDE + 16 * i, gB + (kt) * 32 + 8 * i);\
        CP_COMMIT();                                                   \
    } while (0)

    float c[2][8][4];
#pragma unroll
    for (int i = 0; i < 2; i++)
#pragma unroll
        for (int j = 0; j < 8; j++)
#pragma unroll
            for (int q = 0; q < 4; q++) c[i][j][q] = 0.f;

    ISSUE2(0, 0);
#pragma unroll 1
    for (int kt = 0; kt < 8; ++kt) {
        const int buf = kt & 1;
        if (kt < 7) { ISSUE2(buf ^ 1, kt + 1); CP_WAIT(1); }
        else        { CP_WAIT(0); }
        __syncthreads();
        const __half* A0 = sA + buf * 64 * PADH;
        const __half* B0 = sB + buf * 64 * PADH;
#pragma unroll
        for (int ks = 0; ks < 2; ++ks) {
            const int kb = ks * 16 + 2 * tig;
            uint32_t af[2][4];
#pragma unroll
            for (int ma = 0; ma < 2; ma++) {
                const __half* ar0 = A0 + (warp * 32 + ma * 16 + g) * PADH + kb;
                af[ma][0] = *(const uint32_t*)(ar0);
                af[ma][1] = *(const uint32_t*)(ar0 + 8 * PADH);
                af[ma][2] = *(const uint32_t*)(ar0 + 8);
                af[ma][3] = *(const uint32_t*)(ar0 + 8 * PADH + 8);
            }
#pragma unroll
            for (int j = 0; j < 8; j++) {
                const __half* br0 = B0 + (8 * j + g) * PADH + kb;
                uint32_t b0 = *(const uint32_t*)(br0);
                uint32_t b1 = *(const uint32_t*)(br0 + 8);
                mma16(c[0][j], af[0][0], af[0][1], af[0][2], af[0][3], b0, b1);
                mma16(c[1][j], af[1][0], af[1][1], af[1][2], af[1][3], b0, b1);
            }
        }
        __syncthreads();
    }
#undef ISSUE2

#pragma unroll
    for (int ma = 0; ma < 2; ma++) {
        float slo = 0.f, dlo = 0.f, shi = 0.f, dhi = 0.f;
#pragma unroll
        for (int j = 0; j < 8; j++) {
            const int col = 8 * j + 2 * tig;
            float w0 = sa2[col], w1 = sa2[col + 1];
            float u0 = sa2[64 + col], u1 = sa2[64 + col + 1];
            slo += c[ma][j][0] * w0 + c[ma][j][1] * w1;
            dlo += c[ma][j][0] * u0 + c[ma][j][1] * u1;
            shi += c[ma][j][2] * w0 + c[ma][j][3] * w1;
            dhi += c[ma][j][2] * u0 + c[ma][j][3] * u1;
        }
#pragma unroll
        for (int o = 1; o < 4; o <<= 1) {
            slo += __shfl_xor_sync(0xffffffffu, slo, o);
            dlo += __shfl_xor_sync(0xffffffffu, dlo, o);
            shi += __shfl_xor_sync(0xffffffffu, shi, o);
            dhi += __shfl_xor_sync(0xffffffffu, dhi, o);
        }
        const int rlo = row0 + warp * 32 + ma * 16 + g;
        const int rhi = rlo + 8;
        __half2* dst0 = (__half2*)g_g + (size_t)rlo * 32;
        __half2* dst1 = (__half2*)g_g + (size_t)rhi * 32;
#pragma unroll
        for (int j = 0; j < 8; j++) {
            const int hc = 4 * j + tig;
            dst0[hc] = __floats2half2_rn(c[ma][j][0], c[ma][j][1]);
            dst1[hc] = __floats2half2_rn(c[ma][j][2], c[ma][j][3]);
        }
        if (tig == 0) {
            g_tsrc[rlo] = slo; g_tdst[rlo] = dlo;
            g_tsrc[rhi] = shi; g_tdst[rhi] = dhi;
        }
    }
}

// ---------------- attn2: warp per (b,n), shfl-deduped edge scalars + elu --------
__global__ void attn2_kernel(float* __restrict__ out) {
    int gw   = (blockIdx.x * blockDim.x + threadIdx.x) >> 5;
    int lane = threadIdx.x & 31;
    if (gw >= Bz * Nn) return;
    int n = gw & (Nn - 1);
    int b = gw >> 11;
    int sub = lane & 3;
    const __half2* gb = (const __half2*)g_g + (size_t)b * Nn * 32 + lane;
    const float*   td = g_tdst + (size_t)b * Nn;
    float ti = g_tsrc[gw];
    int dg = g_deg[n];
    const int* cr = g_cols + n * MAX_DEG;
    float2 acc = {0.f, 0.f};
    float den = 0.f;
    int k = 0;
    int4 nx = *(const int4*)cr;
    for (; k + 4 <= dg; k += 4) {
        int4 mm = nx;
        if (k + 8 <= dg) nx = *(const int4*)(cr + k + 4);
        int midx = (sub == 0) ? mm.x : (sub == 1) ? mm.y : (sub == 2) ? mm.z : mm.w;
        float ev = edge_e(ti, td[midx]);
        float e0 = __shfl_sync(0xffffffffu, ev, 0);
        float e1 = __shfl_sync(0xffffffffu, ev, 1);
        float e2 = __shfl_sync(0xffffffffu, ev, 2);
        float e3 = __shfl_sync(0xffffffffu, ev, 3);
        __half2 v0 = gb[(size_t)mm.x * 32];
        __half2 v1 = gb[(size_t)mm.y * 32];
        __half2 v2 = gb[(size_t)mm.z * 32];
        __half2 v3 = gb[(size_t)mm.w * 32];
        den += (e0 + e1) + (e2 + e3);
        float2 f0 = __half22float2(v0), f1 = __half22float2(v1);
        float2 f2 = __half22float2(v2), f3 = __half22float2(v3);
        acc.x += e0 * f0.x + e1 * f1.x + e2 * f2.x + e3 * f3.x;
        acc.y += e0 * f0.y + e1 * f1.y + e2 * f2.y + e3 * f3.y;
    }
    for (; k < dg; k++) {
        int m = cr[k];
        float e = edge_e(ti, td[m]);
        float2 f = __half22float2(gb[(size_t)m * 32]);
        den += e;
        acc.x += e * f.x; acc.y += e * f.y;
    }
    float inv = 1.0f / den;
    float o0 = acc.x * inv, o1 = acc.y * inv;
    o0 = o0 > 0.f ? o0 : expm1f(o0);
    o1 = o1 > 0.f ? o1 : expm1f(o1);
    float* dst = out + (size_t)gw * NC + lane * 2;
    dst[0] = o0; dst[1] = o1;
}

// ---------------- launch -----------------------------------------------------------
extern "C" void kernel_launch(void* const* d_in, const int* in_sizes, int n_in,
                              void* d_out, int out_size) {
    const float* x   = (const float*)d_in[0];
    const float* adj = (const float*)d_in[1];
    const float* W1  = (const float*)d_in[2];
    const float* a1  = (const float*)d_in[3];
    const float* W2  = (const float*)d_in[4];
    const float* a2  = (const float*)d_in[5];
    float* out = (float*)d_out;

    const int smem1 = 4 * 128 * PADH1 * 2 + 512 * 4;  // 75776 B
    const int smem2 = 4 * 64 * PADH * 2 + 128 * 4;    // 20992 B
    cudaFuncSetAttribute(gemm1_mma, cudaFuncAttributeMaxDynamicSharedMemorySize, smem1);
    cudaFuncSetAttribute(gemm2_mma, cudaFuncAttributeMaxDynamicSharedMemorySize, smem2);

    csr_convert_kernel<<<(Nn * 32) / 256, 256>>>(adj, x);
    transposeW1_kernel<<<dim3(16, 2, 4), dim3(32, 8)>>>(W1);
    gemm1_mma<<<dim3(64, 2), 256, smem1>>>(a1);
    attn1_kernel<<<(Bz * Nn * 32) / 256, 256>>>();      // profiled (4th)
    transposeW2_kernel<<<dim3(8, 2), dim3(32, 8)>>>(W2);
    gemm2_mma<<<128, 64, smem2>>>(a2);
    attn2_kernel<<<(Bz * Nn * 32) / 256, 256>>>(out);
}